// round 1
// baseline (speedup 1.0000x reference)
#include <cuda_runtime.h>
#include <cuda_fp16.h>
#include <cstdint>

// ---------------------------------------------------------------------------
// LSTMDiscriminator: only h[batch_split[:-1]] (512 agents) feeds the output,
// and each agent's recurrence is independent -> run LSTM for 512 agents only.
// Input-side GEMM folded:  gates_in = vel @ Wc^T + bc  (Wc: 512x2, bc: 512)
//   Wc = SCALE * W_ih @ W_emb,  bc = W_ih @ b_emb + b_ih + b_hh
// ---------------------------------------------------------------------------

#define GATES   512
#define HID     128
#define EMB     64
#define NSEL    512
#define MAXSTEPS 20
#define AG      16          // agents per LSTM block (one full m16 tile)
#define KP      136         // K pitch in halves (bank-conflict-free)
#define NBLK    (NSEL/AG)   // 32 LSTM blocks

// scratch (static device globals -- no allocation)
__device__ __align__(16) __half g_Wf[GATES * KP];       // W_hh rows, f16, pitched
__device__ float g_Wc[GATES * 3];                        // wc0, wc1, bc
__device__ float g_gin[MAXSTEPS * NSEL * GATES];         // precomputed input gates (21 MB)
__device__ float g_mask[MAXSTEPS * NSEL];                // per (step,row) valid mask
__device__ float g_hfin[NSEL * HID];                     // final hidden states

// ------------------------- prep1: fold weights ----------------------------
__global__ void prep1_kernel(const float* __restrict__ W_ih,
                             const float* __restrict__ W_emb,
                             const float* __restrict__ b_emb,
                             const float* __restrict__ b_ih,
                             const float* __restrict__ b_hh,
                             const float* __restrict__ W_hh) {
    int n = blockIdx.x * blockDim.x + threadIdx.x;
    if (n >= GATES) return;
    float wc0 = 0.f, wc1 = 0.f, bc = 0.f;
    #pragma unroll 4
    for (int e = 0; e < EMB; e++) {
        float w = W_ih[n * EMB + e];
        wc0 += w * W_emb[2 * e + 0];
        wc1 += w * W_emb[2 * e + 1];
        bc  += w * b_emb[e];
    }
    g_Wc[n * 3 + 0] = 4.0f * wc0;   // SCALE = 4
    g_Wc[n * 3 + 1] = 4.0f * wc1;
    g_Wc[n * 3 + 2] = bc + b_ih[n] + b_hh[n];
    #pragma unroll 4
    for (int k = 0; k < HID; k++)
        g_Wf[n * KP + k] = __float2half_rn(W_hh[n * HID + k]);
    for (int k = HID; k < KP; k++)
        g_Wf[n * KP + k] = __float2half_rn(0.f);
}

// -------------- prep2: per-(step,row) input gates + mask -------------------
__global__ void prep2_kernel(const float* __restrict__ obs,
                             const float* __restrict__ pred,
                             const void*  __restrict__ bsplit_raw,
                             int N, int T_obs, int T_pred) {
    __shared__ float s_wc[GATES * 3];
    __shared__ float s_vx[AG], s_vy[AG];
    int t    = blockIdx.y;
    int row0 = blockIdx.x * AG;

    for (int i = threadIdx.x; i < GATES * 3; i += blockDim.x) s_wc[i] = g_Wc[i];

    if (threadIdx.x < AG) {
        int row = row0 + threadIdx.x;
        // batch_split dtype robustness: detect int32 vs int64 via last element
        const int* p32 = (const int*)bsplit_raw;
        int agent;
        if (p32[NSEL] == N) {                      // int32 layout
            agent = p32[row];
        } else {                                   // int64 layout
            agent = (int)((const long long*)bsplit_raw)[row];
        }
        const float* f0 = (t < T_obs)
            ? obs  + ((size_t)t * N + agent) * 2
            : pred + ((size_t)(t - T_obs) * N + agent) * 2;
        int t1 = t + 1;
        const float* f1 = (t1 < T_obs)
            ? obs  + ((size_t)t1 * N + agent) * 2
            : pred + ((size_t)(t1 - T_obs) * N + agent) * 2;
        float x0 = f0[0], y0 = f0[1], x1 = f1[0], y1 = f1[1];
        bool m = !(isnan(x0) || isnan(x1));
        s_vx[threadIdx.x] = m ? (x1 - x0) : 0.f;
        s_vy[threadIdx.x] = m ? (y1 - y0) : 0.f;
        g_mask[t * NSEL + row] = m ? 1.f : 0.f;
    }
    __syncthreads();

    float* gout = g_gin + ((size_t)t * NSEL + row0) * GATES;
    for (int i = threadIdx.x; i < AG * GATES; i += blockDim.x) {
        int al = i >> 9;         // / GATES
        int n  = i & (GATES - 1);
        gout[(size_t)al * GATES + n] =
            s_vx[al] * s_wc[n * 3 + 0] + s_vy[al] * s_wc[n * 3 + 1] + s_wc[n * 3 + 2];
    }
}

// ----------------------------- activations --------------------------------
__device__ __forceinline__ float sigf(float x) {
    return __fdividef(1.f, 1.f + __expf(-x));
}
__device__ __forceinline__ float tanhfast(float x) {
    return __fdividef(2.f, 1.f + __expf(-2.f * x)) - 1.f;
}

// ------------------------------- LSTM core --------------------------------
// block: 16 agents, 256 threads (8 warps). warp w owns hidden units [16w,16w+16).
// gates via mma.sync m16n8k16 f16->f32: A = h (SMEM ping-pong), B = W_hh (SMEM).
__global__ void __launch_bounds__(256, 1) lstm_kernel(int steps) {
    extern __shared__ __half smem[];
    __half* Ws = smem;                  // GATES * KP
    __half* Xs = smem + GATES * KP;     // 2 * AG * KP (h ping-pong)
    __shared__ float s_mask[2][AG];

    const int tid  = threadIdx.x;
    const int w    = tid >> 5;
    const int lane = tid & 31;
    const int r    = lane >> 2;   // groupID
    const int q    = lane & 3;    // threadID in group
    const int row0 = blockIdx.x * AG;
    const int U    = w * 16;

    // load folded W into SMEM (f16), zero h buffers
    for (int i = tid; i < GATES * KP / 2; i += 256)
        ((uint32_t*)Ws)[i] = ((const uint32_t*)g_Wf)[i];
    for (int i = tid; i < 2 * AG * KP / 2; i += 256)
        ((uint32_t*)Xs)[i] = 0u;

    float c[8], h[8];
    #pragma unroll
    for (int p = 0; p < 8; p++) { c[p] = 0.f; h[p] = 0.f; }

    for (int t = 0; t < steps; t++) {
        const int cur = t & 1, nxt = cur ^ 1;
        if (tid < AG) s_mask[cur][tid] = g_mask[t * NSEL + row0 + tid];
        __syncthreads();   // prev-step h writes + mask visible

        // prefetch precomputed input gates (seed values), fp32
        const float* gb = g_gin + ((size_t)t * NSEL + row0) * GATES;
        float gin[8][4];
        #pragma unroll
        for (int s = 0; s < 2; s++) {
            const int u = U + 8 * s + 2 * q;
            #pragma unroll
            for (int gi = 0; gi < 4; gi++) {
                const int n = gi * 128 + u;
                float2 v0 = *(const float2*)(gb + (size_t)r * GATES + n);
                float2 v1 = *(const float2*)(gb + (size_t)(r + 8) * GATES + n);
                const int f = gi * 2 + s;
                gin[f][0] = v0.x; gin[f][1] = v0.y;
                gin[f][2] = v1.x; gin[f][3] = v1.y;
            }
        }

        float d[8][4];
        #pragma unroll
        for (int f = 0; f < 8; f++)
            #pragma unroll
            for (int k = 0; k < 4; k++) d[f][k] = 0.f;

        const __half* Xc = Xs + cur * AG * KP;
        #pragma unroll
        for (int kc = 0; kc < 8; kc++) {
            const int kb = kc * 16 + 2 * q;
            uint32_t a0 = *(const uint32_t*)(Xc + r * KP + kb);
            uint32_t a1 = *(const uint32_t*)(Xc + (r + 8) * KP + kb);
            uint32_t a2 = *(const uint32_t*)(Xc + r * KP + kb + 8);
            uint32_t a3 = *(const uint32_t*)(Xc + (r + 8) * KP + kb + 8);
            #pragma unroll
            for (int f = 0; f < 8; f++) {
                const int gi = f >> 1, s = f & 1;
                const int nb = gi * 128 + U + 8 * s;
                const __half* bp = Ws + (nb + r) * KP + kb;
                uint32_t b0 = *(const uint32_t*)(bp);
                uint32_t b1 = *(const uint32_t*)(bp + 8);
                asm volatile(
                    "mma.sync.aligned.m16n8k16.row.col.f32.f16.f16.f32 "
                    "{%0,%1,%2,%3},{%4,%5,%6,%7},{%8,%9},{%0,%1,%2,%3};"
                    : "+f"(d[f][0]), "+f"(d[f][1]), "+f"(d[f][2]), "+f"(d[f][3])
                    : "r"(a0), "r"(a1), "r"(a2), "r"(a3), "r"(b0), "r"(b1));
            }
        }

        // epilogue: activations + cell update + write h (f16) to next buffer
        __half* Xn = Xs + nxt * AG * KP;
        #pragma unroll
        for (int s = 0; s < 2; s++) {
            const int u = U + 8 * s + 2 * q;
            #pragma unroll
            for (int ar = 0; ar < 2; ar++) {
                const int a = r + 8 * ar;
                const float m = s_mask[cur][a];
                float hv[2];
                #pragma unroll
                for (int j = 0; j < 2; j++) {
                    const int k = ar * 2 + j;
                    const int p = s * 4 + ar * 2 + j;
                    float iv = sigf    (d[0 + s][k] + gin[0 + s][k]);
                    float fv = sigf    (d[2 + s][k] + gin[2 + s][k]);
                    float gv = tanhfast(d[4 + s][k] + gin[4 + s][k]);
                    float ov = sigf    (d[6 + s][k] + gin[6 + s][k]);
                    float c2 = fv * c[p] + iv * gv;
                    float h2 = ov * tanhfast(c2);
                    if (m != 0.f) { c[p] = c2; h[p] = h2; }
                    hv[j] = h[p];
                }
                *(__half2*)(Xn + a * KP + u) = __floats2half2_rn(hv[0], hv[1]);
            }
        }
    }

    // write final hidden state (fp32) for the MLP
    #pragma unroll
    for (int s = 0; s < 2; s++)
        #pragma unroll
        for (int ar = 0; ar < 2; ar++)
            #pragma unroll
            for (int j = 0; j < 2; j++) {
                const int u = U + 8 * s + 2 * q + j;
                const int a = r + 8 * ar;
                g_hfin[(size_t)(row0 + a) * HID + u] = h[s * 4 + ar * 2 + j];
            }
}

// ------------------------------- MLP head ---------------------------------
__global__ void mlp_kernel(const float* __restrict__ W1, const float* __restrict__ b1,
                           const float* __restrict__ W2, const float* __restrict__ b2,
                           const float* __restrict__ W3, const float* __restrict__ b3,
                           float* __restrict__ out) {
    __shared__ float sh[HID];
    __shared__ float sx1[64];
    __shared__ float sx2[32];
    const int s = blockIdx.x, tid = threadIdx.x;
    if (tid < HID) sh[tid] = g_hfin[(size_t)s * HID + tid];
    __syncthreads();
    if (tid < 64) {
        float acc = b1[tid];
        const float* wr = W1 + (size_t)tid * HID;
        #pragma unroll 8
        for (int k = 0; k < HID; k += 4) {
            float4 wv = *(const float4*)(wr + k);
            acc += wv.x * sh[k] + wv.y * sh[k + 1] + wv.z * sh[k + 2] + wv.w * sh[k + 3];
        }
        sx1[tid] = fmaxf(acc, 0.f);
    }
    __syncthreads();
    if (tid < 32) {
        float acc = b2[tid];
        const float* wr = W2 + (size_t)tid * 64;
        #pragma unroll 8
        for (int k = 0; k < 64; k++) acc += wr[k] * sx1[k];
        sx2[tid] = fmaxf(acc, 0.f);
    }
    __syncthreads();
    if (tid == 0) {
        float acc = b3[0];
        #pragma unroll
        for (int k = 0; k < 32; k++) acc += W3[k] * sx2[k];
        out[s] = fmaxf(acc, 0.f);
    }
}

// ------------------------------- launcher ----------------------------------
extern "C" void kernel_launch(void* const* d_in, const int* in_sizes, int n_in,
                              void* d_out, int out_size) {
    const float* observed   = (const float*)d_in[0];
    const float* prediction = (const float*)d_in[1];
    const void*  bsplit     = d_in[3];
    const float* W_emb      = (const float*)d_in[4];
    const float* b_emb      = (const float*)d_in[5];
    const float* W_ih       = (const float*)d_in[6];
    const float* W_hh       = (const float*)d_in[7];
    const float* b_ih       = (const float*)d_in[8];
    const float* b_hh       = (const float*)d_in[9];
    const float* W1         = (const float*)d_in[10];
    const float* b1         = (const float*)d_in[11];
    const float* W2         = (const float*)d_in[12];
    const float* b2         = (const float*)d_in[13];
    const float* W3         = (const float*)d_in[14];
    const float* b3         = (const float*)d_in[15];
    float* out = (float*)d_out;

    const int N      = in_sizes[2] / 2;               // goals: (N,2)
    const int T_obs  = in_sizes[0] / (2 * N);
    const int T_pred = in_sizes[1] / (2 * N);
    int steps = T_obs + T_pred - 1;
    if (steps > MAXSTEPS) steps = MAXSTEPS;

    prep1_kernel<<<(GATES + 127) / 128, 128>>>(W_ih, W_emb, b_emb, b_ih, b_hh, W_hh);

    dim3 g2(NBLK, steps);
    prep2_kernel<<<g2, 256>>>(observed, prediction, bsplit, N, T_obs, T_pred);

    size_t smem_bytes = (size_t)(GATES * KP + 2 * AG * KP) * sizeof(__half);
    cudaFuncSetAttribute(lstm_kernel, cudaFuncAttributeMaxDynamicSharedMemorySize,
                         (int)smem_bytes);
    lstm_kernel<<<NBLK, 256, smem_bytes>>>(steps);

    mlp_kernel<<<NSEL, 128>>>(W1, b1, W2, b2, W3, b3, out);
}

// round 2
// speedup vs baseline: 1.4913x; 1.4913x over previous
#include <cuda_runtime.h>
#include <cuda_fp16.h>
#include <cstdint>

// ---------------------------------------------------------------------------
// Fully fused LSTMDiscriminator. Only h[batch_split[:-1]] (512 agents) feeds
// the output -> run the recurrence for those 512 agents only.
// Input-side GEMM folded: gates_in = vx*wc0[n] + vy*wc1[n] + bc[n], computed
// on the fly per step (no 21MB staging buffer). MLP fused into block tail.
// ---------------------------------------------------------------------------

#define GATES    512
#define HID      128
#define EMB      64
#define NSEL     512
#define MAXSTEPS 20
#define AG       16          // agents per block (one m16 MMA tile)
#define KP       136         // K pitch in halves (bank-conflict avoidance)
#define NBLK     (NSEL/AG)   // 32 blocks

// SMEM layout (bytes):
//   Ws    : GATES*KP*2            = 139264   (W_hh f16, pitched)
//   Xs    : 2*AG*KP*2             = 8704     (h ping-pong, f16)
//   s_wc  : GATES*16              = 8192     (wc0,wc1,bc,pad per gate)
//   s_pos : (MAXSTEPS+1)*AG*2*4   = 2688     (agent positions)
//   sh    : AG*HID*4              = 8192     (final h, fp32)
//   s1    : AG*64*4               = 4096
//   s2    : AG*32*4               = 2048
#define OFF_WS   0
#define OFF_XS   139264
#define OFF_WC   (OFF_XS + 8704)
#define OFF_POS  (OFF_WC + 8192)
#define OFF_SH   (OFF_POS + 2688)
#define OFF_S1   (OFF_SH + 8192)
#define OFF_S2   (OFF_S1 + 4096)
#define SMEM_TOTAL (OFF_S2 + 2048)

__device__ __forceinline__ float sigf(float x) {
    return __fdividef(1.f, 1.f + __expf(-x));
}
__device__ __forceinline__ float tanhfast(float x) {
    return __fdividef(2.f, 1.f + __expf(-2.f * x)) - 1.f;
}

__global__ void __launch_bounds__(256, 1) fused_kernel(
    const float* __restrict__ obs, const float* __restrict__ pred,
    const void*  __restrict__ bsplit,
    const float* __restrict__ W_emb, const float* __restrict__ b_emb,
    const float* __restrict__ W_ih,  const float* __restrict__ W_hh,
    const float* __restrict__ b_ih,  const float* __restrict__ b_hh,
    const float* __restrict__ W1, const float* __restrict__ b1,
    const float* __restrict__ W2, const float* __restrict__ b2,
    const float* __restrict__ W3, const float* __restrict__ b3,
    float* __restrict__ out,
    int N, int T_obs, int steps)
{
    extern __shared__ char smraw[];
    __half* Ws    = (__half*)(smraw + OFF_WS);
    __half* Xs    = (__half*)(smraw + OFF_XS);
    float4* s_wc  = (float4*)(smraw + OFF_WC);
    float*  s_pos = (float*) (smraw + OFF_POS);
    float*  sh    = (float*) (smraw + OFF_SH);
    float*  s1    = (float*) (smraw + OFF_S1);
    float*  s2    = (float*) (smraw + OFF_S2);
    __shared__ int s_agent[AG];

    const int tid  = threadIdx.x;
    const int w    = tid >> 5;
    const int lane = tid & 31;
    const int r    = lane >> 2;   // MMA groupID (row within tile)
    const int q    = lane & 3;    // threadID in group
    const int row0 = blockIdx.x * AG;
    const int U    = w * 16;      // hidden-unit base for this warp

    // ---- prologue 1: W_hh fp32 -> f16 SMEM (pitched) ----
    for (int i = tid; i < GATES * HID / 4; i += 256) {
        float4 v = ((const float4*)W_hh)[i];
        int row = i >> 5;            // / (HID/4)
        int c4  = (i & 31) << 2;
        __half* p = Ws + row * KP + c4;
        *(__half2*)(p)     = __floats2half2_rn(v.x, v.y);
        *(__half2*)(p + 2) = __floats2half2_rn(v.z, v.w);
    }

    // ---- prologue 2: fold input-side weights ----
    // wc0 = SCALE * W_ih @ W_emb[:,0], wc1 likewise, bc = W_ih@b_emb + b_ih + b_hh
    for (int n = tid; n < GATES; n += 256) {
        float wc0 = 0.f, wc1 = 0.f, bc = 0.f;
        const float* wr = W_ih + (size_t)n * EMB;
        #pragma unroll 4
        for (int e = 0; e < EMB; e++) {
            float ww = wr[e];
            wc0 += ww * W_emb[2 * e + 0];
            wc1 += ww * W_emb[2 * e + 1];
            bc  += ww * b_emb[e];
        }
        s_wc[n] = make_float4(4.0f * wc0, 4.0f * wc1, bc + b_ih[n] + b_hh[n], 0.f);
    }

    // ---- prologue 3: gather agent indices + positions ----
    if (tid < AG) {
        int row = row0 + tid;
        const int* p32 = (const int*)bsplit;           // dtype-robust
        int agent = (p32[NSEL] == N) ? p32[row]
                                     : (int)((const long long*)bsplit)[row];
        s_agent[tid] = agent;
    }
    __syncthreads();
    for (int i = tid; i < (steps + 1) * AG; i += 256) {
        int t = i / AG, al = i % AG;
        int agent = s_agent[al];
        const float* f = (t < T_obs)
            ? obs  + ((size_t)t * N + agent) * 2
            : pred + ((size_t)(t - T_obs) * N + agent) * 2;
        s_pos[i * 2 + 0] = f[0];
        s_pos[i * 2 + 1] = f[1];
    }

    // ---- prologue 4: zero h ping-pong ----
    for (int i = tid; i < 2 * AG * KP / 2; i += 256)
        ((uint32_t*)Xs)[i] = 0u;

    __syncthreads();

    // ---- hoist folded coefficients into registers (48 regs) ----
    // gate index for frag f (gi=f>>1, s=f&1), lane element j: n = gi*128+U+8s+2q+j
    float w0r[8][2], w1r[8][2], bcr[8][2];
    #pragma unroll
    for (int f = 0; f < 8; f++) {
        const int gi = f >> 1, s = f & 1;
        #pragma unroll
        for (int j = 0; j < 2; j++) {
            float4 wc = s_wc[gi * 128 + U + 8 * s + 2 * q + j];
            w0r[f][j] = wc.x; w1r[f][j] = wc.y; bcr[f][j] = wc.z;
        }
    }

    float c[8], h[8];
    #pragma unroll
    for (int p = 0; p < 8; p++) { c[p] = 0.f; h[p] = 0.f; }

    // =========================== recurrence ===============================
    for (int t = 0; t < steps; t++) {
        const int cur = t & 1, nxt = cur ^ 1;
        __syncthreads();   // prev-step h writes visible

        // velocities + masks for agents r and r+8 (from SMEM positions)
        float2 p0a = *(const float2*)(s_pos + ((t    ) * AG + r) * 2);
        float2 p1a = *(const float2*)(s_pos + ((t + 1) * AG + r) * 2);
        float2 p0b = *(const float2*)(s_pos + ((t    ) * AG + r + 8) * 2);
        float2 p1b = *(const float2*)(s_pos + ((t + 1) * AG + r + 8) * 2);
        bool  m0 = !(isnan(p0a.x) || isnan(p1a.x));
        bool  m1 = !(isnan(p0b.x) || isnan(p1b.x));
        float vx0 = m0 ? (p1a.x - p0a.x) : 0.f, vy0 = m0 ? (p1a.y - p0a.y) : 0.f;
        float vx1 = m1 ? (p1b.x - p0b.x) : 0.f, vy1 = m1 ? (p1b.y - p0b.y) : 0.f;

        // accumulators seeded with on-the-fly input gates
        float d[8][4];
        #pragma unroll
        for (int f = 0; f < 8; f++) {
            d[f][0] = vx0 * w0r[f][0] + vy0 * w1r[f][0] + bcr[f][0];
            d[f][1] = vx0 * w0r[f][1] + vy0 * w1r[f][1] + bcr[f][1];
            d[f][2] = vx1 * w0r[f][0] + vy1 * w1r[f][0] + bcr[f][0];
            d[f][3] = vx1 * w0r[f][1] + vy1 * w1r[f][1] + bcr[f][1];
        }

        // gates += h @ W_hh^T  via m16n8k16 f16->f32
        const __half* Xc = Xs + cur * AG * KP;
        #pragma unroll
        for (int kc = 0; kc < 8; kc++) {
            const int kb = kc * 16 + 2 * q;
            uint32_t a0 = *(const uint32_t*)(Xc + r * KP + kb);
            uint32_t a1 = *(const uint32_t*)(Xc + (r + 8) * KP + kb);
            uint32_t a2 = *(const uint32_t*)(Xc + r * KP + kb + 8);
            uint32_t a3 = *(const uint32_t*)(Xc + (r + 8) * KP + kb + 8);
            #pragma unroll
            for (int f = 0; f < 8; f++) {
                const int gi = f >> 1, s = f & 1;
                const int nb = gi * 128 + U + 8 * s;
                const __half* bp = Ws + (nb + r) * KP + kb;
                uint32_t b0 = *(const uint32_t*)(bp);
                uint32_t b1 = *(const uint32_t*)(bp + 8);
                asm volatile(
                    "mma.sync.aligned.m16n8k16.row.col.f32.f16.f16.f32 "
                    "{%0,%1,%2,%3},{%4,%5,%6,%7},{%8,%9},{%0,%1,%2,%3};"
                    : "+f"(d[f][0]), "+f"(d[f][1]), "+f"(d[f][2]), "+f"(d[f][3])
                    : "r"(a0), "r"(a1), "r"(a2), "r"(a3), "r"(b0), "r"(b1));
            }
        }

        // epilogue: activations + cell update + write h(f16) to next buffer
        __half* Xn = Xs + nxt * AG * KP;
        #pragma unroll
        for (int s = 0; s < 2; s++) {
            const int u = U + 8 * s + 2 * q;
            #pragma unroll
            for (int ar = 0; ar < 2; ar++) {
                const int a = r + 8 * ar;
                const bool m = ar ? m1 : m0;
                float hv[2];
                #pragma unroll
                for (int j = 0; j < 2; j++) {
                    const int k = ar * 2 + j;
                    const int p = s * 4 + ar * 2 + j;
                    float iv = sigf    (d[0 + s][k]);
                    float fv = sigf    (d[2 + s][k]);
                    float gv = tanhfast(d[4 + s][k]);
                    float ov = sigf    (d[6 + s][k]);
                    float c2 = fv * c[p] + iv * gv;
                    float h2 = ov * tanhfast(c2);
                    if (m) { c[p] = c2; h[p] = h2; }
                    hv[j] = h[p];
                }
                *(__half2*)(Xn + a * KP + u) = __floats2half2_rn(hv[0], hv[1]);
            }
        }
    }

    // =========================== fused MLP tail ===========================
    // spill final h (fp32) to SMEM
    #pragma unroll
    for (int s = 0; s < 2; s++)
        #pragma unroll
        for (int ar = 0; ar < 2; ar++)
            #pragma unroll
            for (int j = 0; j < 2; j++) {
                const int u = U + 8 * s + 2 * q + j;
                const int a = r + 8 * ar;
                sh[a * HID + u] = h[s * 4 + ar * 2 + j];
            }
    __syncthreads();

    // layer 1: (16 x 128) @ W1^T(64x128) -> relu -> s1[16][64]
    {
        const int u  = tid & 63;
        const int a0 = (tid >> 6) * 4;          // 4 agents per thread, shared W1 row
        float acc[4];
        #pragma unroll
        for (int i = 0; i < 4; i++) acc[i] = b1[u];
        const float* wr = W1 + (size_t)u * HID;
        #pragma unroll 8
        for (int k = 0; k < HID; k += 4) {
            float4 wv = *(const float4*)(wr + k);
            #pragma unroll
            for (int i = 0; i < 4; i++) {
                float4 hv = *(const float4*)(sh + (a0 + i) * HID + k);
                acc[i] += wv.x * hv.x + wv.y * hv.y + wv.z * hv.z + wv.w * hv.w;
            }
        }
        #pragma unroll
        for (int i = 0; i < 4; i++)
            s1[(a0 + i) * 64 + u] = fmaxf(acc[i], 0.f);
    }
    __syncthreads();

    // layer 2: (16 x 64) @ W2^T(32x64) -> relu -> s2[16][32]
    {
        const int u  = tid & 31;
        const int a0 = (tid >> 5) * 2;          // 2 agents per thread
        float acc[2] = { b2[u], b2[u] };
        const float* wr = W2 + (size_t)u * 64;
        #pragma unroll 4
        for (int k = 0; k < 64; k += 4) {
            float4 wv = *(const float4*)(wr + k);
            #pragma unroll
            for (int i = 0; i < 2; i++) {
                float4 hv = *(const float4*)(s1 + (a0 + i) * 64 + k);
                acc[i] += wv.x * hv.x + wv.y * hv.y + wv.z * hv.z + wv.w * hv.w;
            }
        }
        #pragma unroll
        for (int i = 0; i < 2; i++)
            s2[(a0 + i) * 32 + u] = fmaxf(acc[i], 0.f);
    }
    __syncthreads();

    // layer 3: (16 x 32) @ W3^T(1x32) -> relu -> out
    if (tid < AG) {
        float acc = b3[0];
        #pragma unroll
        for (int k = 0; k < 32; k++) acc += W3[k] * s2[tid * 32 + k];
        out[row0 + tid] = fmaxf(acc, 0.f);
    }
}

// ------------------------------- launcher ----------------------------------
extern "C" void kernel_launch(void* const* d_in, const int* in_sizes, int n_in,
                              void* d_out, int out_size) {
    const float* observed   = (const float*)d_in[0];
    const float* prediction = (const float*)d_in[1];
    const void*  bsplit     = d_in[3];
    const float* W_emb      = (const float*)d_in[4];
    const float* b_emb      = (const float*)d_in[5];
    const float* W_ih       = (const float*)d_in[6];
    const float* W_hh       = (const float*)d_in[7];
    const float* b_ih       = (const float*)d_in[8];
    const float* b_hh       = (const float*)d_in[9];
    const float* W1         = (const float*)d_in[10];
    const float* b1         = (const float*)d_in[11];
    const float* W2         = (const float*)d_in[12];
    const float* b2         = (const float*)d_in[13];
    const float* W3         = (const float*)d_in[14];
    const float* b3         = (const float*)d_in[15];
    float* out = (float*)d_out;

    const int N      = in_sizes[2] / 2;               // goals: (N,2)
    const int T_obs  = in_sizes[0] / (2 * N);
    const int T_pred = in_sizes[1] / (2 * N);
    int steps = T_obs + T_pred - 1;
    if (steps > MAXSTEPS) steps = MAXSTEPS;

    static int attr_done = 0;
    cudaFuncSetAttribute(fused_kernel, cudaFuncAttributeMaxDynamicSharedMemorySize,
                         SMEM_TOTAL);
    (void)attr_done;

    fused_kernel<<<NBLK, 256, SMEM_TOTAL>>>(
        observed, prediction, bsplit,
        W_emb, b_emb, W_ih, W_hh, b_ih, b_hh,
        W1, b1, W2, b2, W3, b3,
        out, N, T_obs, steps);
}

// round 3
// speedup vs baseline: 1.5460x; 1.0367x over previous
#include <cuda_runtime.h>
#include <cuda_fp16.h>
#include <cstdint>

// ---------------------------------------------------------------------------
// Fully fused LSTMDiscriminator, 512 threads/block (16 warps, 4/SMSP).
// Warp w owns hidden units [8w, 8w+8) for all 4 gates (4 MMA frags).
// B fragments for kc 0..3 register-resident; tanh.approx activations.
// ---------------------------------------------------------------------------

#define GATES    512
#define HID      128
#define EMB      64
#define NSEL     512
#define MAXSTEPS 20
#define AG       16          // agents per block (one m16 MMA tile)
#define KP       136         // K pitch in halves (bank-conflict avoidance)
#define NBLK     (NSEL/AG)   // 32 blocks
#define NTHR     512

#define OFF_WS   0
#define OFF_XS   139264                 // GATES*KP*2
#define OFF_WC   (OFF_XS + 8704)        // 2*AG*KP*2
#define OFF_POS  (OFF_WC + 8192)        // GATES*16
#define OFF_SH   (OFF_POS + 2688)       // (MAXSTEPS+1)*AG*2*4
#define OFF_S1   (OFF_SH + 8192)        // AG*HID*4
#define OFF_S2   (OFF_S1 + 4096)        // AG*64*4
#define SMEM_TOTAL (OFF_S2 + 2048)      // + AG*32*4

__device__ __forceinline__ float tanha(float x) {
    float y;
    asm("tanh.approx.f32 %0, %1;" : "=f"(y) : "f"(x));
    return y;
}
__device__ __forceinline__ float sigf(float x) {
    return fmaf(tanha(0.5f * x), 0.5f, 0.5f);
}

__global__ void __launch_bounds__(NTHR, 1) fused_kernel(
    const float* __restrict__ obs, const float* __restrict__ pred,
    const void*  __restrict__ bsplit,
    const float* __restrict__ W_emb, const float* __restrict__ b_emb,
    const float* __restrict__ W_ih,  const float* __restrict__ W_hh,
    const float* __restrict__ b_ih,  const float* __restrict__ b_hh,
    const float* __restrict__ W1, const float* __restrict__ b1,
    const float* __restrict__ W2, const float* __restrict__ b2,
    const float* __restrict__ W3, const float* __restrict__ b3,
    float* __restrict__ out,
    int N, int T_obs, int steps)
{
    extern __shared__ char smraw[];
    __half* Ws    = (__half*)(smraw + OFF_WS);
    __half* Xs    = (__half*)(smraw + OFF_XS);
    float4* s_wc  = (float4*)(smraw + OFF_WC);
    float*  s_pos = (float*) (smraw + OFF_POS);
    float*  sh    = (float*) (smraw + OFF_SH);
    float*  s1    = (float*) (smraw + OFF_S1);
    float*  s2    = (float*) (smraw + OFF_S2);
    __shared__ int s_agent[AG];

    const int tid  = threadIdx.x;
    const int w    = tid >> 5;           // 0..15
    const int lane = tid & 31;
    const int r    = lane >> 2;          // MMA groupID (0..7)
    const int q    = lane & 3;
    const int row0 = blockIdx.x * AG;
    const int U    = w * 8;              // hidden-unit base for this warp

    // ---- prologue 1: W_hh fp32 -> f16 SMEM (pitched) ----
    for (int i = tid; i < GATES * HID / 4; i += NTHR) {
        float4 v = ((const float4*)W_hh)[i];
        int row = i >> 5;
        int c4  = (i & 31) << 2;
        __half* p = Ws + row * KP + c4;
        *(__half2*)(p)     = __floats2half2_rn(v.x, v.y);
        *(__half2*)(p + 2) = __floats2half2_rn(v.z, v.w);
    }

    // ---- prologue 2: fold input-side weights ----
    for (int n = tid; n < GATES; n += NTHR) {
        float wc0 = 0.f, wc1 = 0.f, bc = 0.f;
        const float* wr = W_ih + (size_t)n * EMB;
        #pragma unroll 4
        for (int e = 0; e < EMB; e++) {
            float ww = wr[e];
            wc0 += ww * W_emb[2 * e + 0];
            wc1 += ww * W_emb[2 * e + 1];
            bc  += ww * b_emb[e];
        }
        s_wc[n] = make_float4(4.0f * wc0, 4.0f * wc1, bc + b_ih[n] + b_hh[n], 0.f);
    }

    // ---- prologue 3: agent indices + positions ----
    if (tid < AG) {
        int row = row0 + tid;
        const int* p32 = (const int*)bsplit;   // dtype-robust int32/int64
        int agent = (p32[NSEL] == N) ? p32[row]
                                     : (int)((const long long*)bsplit)[row];
        s_agent[tid] = agent;
    }
    __syncthreads();
    for (int i = tid; i < (steps + 1) * AG; i += NTHR) {
        int t = i / AG, al = i % AG;
        int agent = s_agent[al];
        const float* f = (t < T_obs)
            ? obs  + ((size_t)t * N + agent) * 2
            : pred + ((size_t)(t - T_obs) * N + agent) * 2;
        s_pos[i * 2 + 0] = f[0];
        s_pos[i * 2 + 1] = f[1];
    }

    // ---- prologue 4: zero h ping-pong ----
    for (int i = tid; i < 2 * AG * KP / 2; i += NTHR)
        ((uint32_t*)Xs)[i] = 0u;

    __syncthreads();

    // ---- hoist input-fold coefficients (frag f = gate f, units U+2q+j) ----
    float w0r[4][2], w1r[4][2], bcr[4][2];
    #pragma unroll
    for (int f = 0; f < 4; f++)
        #pragma unroll
        for (int j = 0; j < 2; j++) {
            float4 wc = s_wc[f * 128 + U + 2 * q + j];
            w0r[f][j] = wc.x; w1r[f][j] = wc.y; bcr[f][j] = wc.z;
        }

    // ---- hoist B fragments for kc 0..3 into registers (32 regs) ----
    uint32_t breg[4][4][2];
    #pragma unroll
    for (int kc = 0; kc < 4; kc++)
        #pragma unroll
        for (int f = 0; f < 4; f++) {
            const __half* bp = Ws + (f * 128 + U + r) * KP + kc * 16 + 2 * q;
            breg[kc][f][0] = *(const uint32_t*)(bp);
            breg[kc][f][1] = *(const uint32_t*)(bp + 8);
        }

    float c[4], h[4];
    #pragma unroll
    for (int p = 0; p < 4; p++) { c[p] = 0.f; h[p] = 0.f; }

    // =========================== recurrence ===============================
    for (int t = 0; t < steps; t++) {
        const int cur = t & 1, nxt = cur ^ 1;
        __syncthreads();   // prev-step h writes visible

        // velocities + masks for agents r and r+8
        float2 p0a = *(const float2*)(s_pos + ((t    ) * AG + r) * 2);
        float2 p1a = *(const float2*)(s_pos + ((t + 1) * AG + r) * 2);
        float2 p0b = *(const float2*)(s_pos + ((t    ) * AG + r + 8) * 2);
        float2 p1b = *(const float2*)(s_pos + ((t + 1) * AG + r + 8) * 2);
        bool  m0 = !(isnan(p0a.x) || isnan(p1a.x));
        bool  m1 = !(isnan(p0b.x) || isnan(p1b.x));
        float vx0 = m0 ? (p1a.x - p0a.x) : 0.f, vy0 = m0 ? (p1a.y - p0a.y) : 0.f;
        float vx1 = m1 ? (p1b.x - p0b.x) : 0.f, vy1 = m1 ? (p1b.y - p0b.y) : 0.f;

        // accumulators seeded with on-the-fly input gates
        float d[4][4];
        #pragma unroll
        for (int f = 0; f < 4; f++) {
            d[f][0] = fmaf(vx0, w0r[f][0], fmaf(vy0, w1r[f][0], bcr[f][0]));
            d[f][1] = fmaf(vx0, w0r[f][1], fmaf(vy0, w1r[f][1], bcr[f][1]));
            d[f][2] = fmaf(vx1, w0r[f][0], fmaf(vy1, w1r[f][0], bcr[f][0]));
            d[f][3] = fmaf(vx1, w0r[f][1], fmaf(vy1, w1r[f][1], bcr[f][1]));
        }

        // gates += h @ W_hh^T  via m16n8k16 f16->f32
        const __half* Xc = Xs + cur * AG * KP;
        #pragma unroll
        for (int kc = 0; kc < 8; kc++) {
            const int kb = kc * 16 + 2 * q;
            uint32_t a0 = *(const uint32_t*)(Xc + r * KP + kb);
            uint32_t a1 = *(const uint32_t*)(Xc + (r + 8) * KP + kb);
            uint32_t a2 = *(const uint32_t*)(Xc + r * KP + kb + 8);
            uint32_t a3 = *(const uint32_t*)(Xc + (r + 8) * KP + kb + 8);
            #pragma unroll
            for (int f = 0; f < 4; f++) {
                uint32_t b0, b1;
                if (kc < 4) {
                    b0 = breg[kc][f][0];
                    b1 = breg[kc][f][1];
                } else {
                    const __half* bp = Ws + (f * 128 + U + r) * KP + kb;
                    b0 = *(const uint32_t*)(bp);
                    b1 = *(const uint32_t*)(bp + 8);
                }
                asm volatile(
                    "mma.sync.aligned.m16n8k16.row.col.f32.f16.f16.f32 "
                    "{%0,%1,%2,%3},{%4,%5,%6,%7},{%8,%9},{%0,%1,%2,%3};"
                    : "+f"(d[f][0]), "+f"(d[f][1]), "+f"(d[f][2]), "+f"(d[f][3])
                    : "r"(a0), "r"(a1), "r"(a2), "r"(a3), "r"(b0), "r"(b1));
            }
        }

        // epilogue: activations + cell update + write h(f16) to next buffer
        __half* Xn = Xs + nxt * AG * KP;
        #pragma unroll
        for (int ar = 0; ar < 2; ar++) {
            const int a = r + 8 * ar;
            const bool m = ar ? m1 : m0;
            float hv[2];
            #pragma unroll
            for (int j = 0; j < 2; j++) {
                const int k = ar * 2 + j;
                const int p = ar * 2 + j;
                float iv = sigf (d[0][k]);
                float fv = sigf (d[1][k]);
                float gv = tanha(d[2][k]);
                float ov = sigf (d[3][k]);
                float c2 = fmaf(fv, c[p], iv * gv);
                float h2 = ov * tanha(c2);
                if (m) { c[p] = c2; h[p] = h2; }
                hv[j] = h[p];
            }
            *(__half2*)(Xn + a * KP + U + 2 * q) = __floats2half2_rn(hv[0], hv[1]);
        }
    }

    // =========================== fused MLP tail ===========================
    #pragma unroll
    for (int ar = 0; ar < 2; ar++)
        #pragma unroll
        for (int j = 0; j < 2; j++)
            sh[(r + 8 * ar) * HID + U + 2 * q + j] = h[ar * 2 + j];
    __syncthreads();

    // layer 1: (16 x 128) @ W1^T(64x128) -> relu -> s1[16][64]
    {
        const int u  = tid & 63;
        const int a0 = (tid >> 6) * 2;          // 2 agents per thread
        float acc[2];
        acc[0] = b1[u]; acc[1] = acc[0];
        const float* wr = W1 + (size_t)u * HID;
        #pragma unroll 8
        for (int k = 0; k < HID; k += 4) {
            float4 wv = *(const float4*)(wr + k);
            #pragma unroll
            for (int i = 0; i < 2; i++) {
                float4 hv = *(const float4*)(sh + (a0 + i) * HID + k);
                acc[i] += wv.x * hv.x + wv.y * hv.y + wv.z * hv.z + wv.w * hv.w;
            }
        }
        #pragma unroll
        for (int i = 0; i < 2; i++)
            s1[(a0 + i) * 64 + u] = fmaxf(acc[i], 0.f);
    }
    __syncthreads();

    // layer 2: (16 x 64) @ W2^T(32x64) -> relu -> s2[16][32]
    {
        const int u = tid & 31;
        const int a = tid >> 5;                 // 16 agents, 1 per warp-group
        float acc = b2[u];
        const float* wr = W2 + (size_t)u * 64;
        #pragma unroll 4
        for (int k = 0; k < 64; k += 4) {
            float4 wv = *(const float4*)(wr + k);
            float4 hv = *(const float4*)(s1 + a * 64 + k);
            acc += wv.x * hv.x + wv.y * hv.y + wv.z * hv.z + wv.w * hv.w;
        }
        s2[a * 32 + u] = fmaxf(acc, 0.f);
    }
    __syncthreads();

    // layer 3: (16 x 32) @ W3^T(1x32) -> relu -> out
    if (tid < AG) {
        float acc = b3[0];
        #pragma unroll
        for (int k = 0; k < 32; k++) acc += W3[k] * s2[tid * 32 + k];
        out[row0 + tid] = fmaxf(acc, 0.f);
    }
}

// ------------------------------- launcher ----------------------------------
extern "C" void kernel_launch(void* const* d_in, const int* in_sizes, int n_in,
                              void* d_out, int out_size) {
    const float* observed   = (const float*)d_in[0];
    const float* prediction = (const float*)d_in[1];
    const void*  bsplit     = d_in[3];
    const float* W_emb      = (const float*)d_in[4];
    const float* b_emb      = (const float*)d_in[5];
    const float* W_ih       = (const float*)d_in[6];
    const float* W_hh       = (const float*)d_in[7];
    const float* b_ih       = (const float*)d_in[8];
    const float* b_hh       = (const float*)d_in[9];
    const float* W1         = (const float*)d_in[10];
    const float* b1         = (const float*)d_in[11];
    const float* W2         = (const float*)d_in[12];
    const float* b2         = (const float*)d_in[13];
    const float* W3         = (const float*)d_in[14];
    const float* b3         = (const float*)d_in[15];
    float* out = (float*)d_out;

    const int N      = in_sizes[2] / 2;               // goals: (N,2)
    const int T_obs  = in_sizes[0] / (2 * N);
    const int T_pred = in_sizes[1] / (2 * N);
    int steps = T_obs + T_pred - 1;
    if (steps > MAXSTEPS) steps = MAXSTEPS;

    cudaFuncSetAttribute(fused_kernel, cudaFuncAttributeMaxDynamicSharedMemorySize,
                         SMEM_TOTAL);

    fused_kernel<<<NBLK, NTHR, SMEM_TOTAL>>>(
        observed, prediction, bsplit,
        W_emb, b_emb, W_ih, W_hh, b_ih, b_hh,
        W1, b1, W2, b2, W3, b3,
        out, N, T_obs, steps);
}

// round 4
// speedup vs baseline: 1.9211x; 1.2426x over previous
#include <cuda_runtime.h>
#include <cuda_fp16.h>
#include <cstdint>

// ---------------------------------------------------------------------------
// Fused LSTMDiscriminator, round 4: MMA transposed (gates on M, agents on N).
// A-operand = W_hh (step-invariant) lives entirely in registers (64 regs).
// B-operand = h (8 agents) -> 16 LDS.32 per warp per step.
// 64 blocks x 512 threads; warp w owns unit lane u = 8w + r for all 4 gates.
// ---------------------------------------------------------------------------

#define GATES    512
#define HID      128
#define EMB      64
#define NSEL     512
#define MAXSTEPS 20
#define AG       8           // agents per block (one n8 MMA tile)
#define KP       136         // pitch in halves
#define NBLK     (NSEL/AG)   // 64 blocks
#define NTHR     512

#define OFF_WS   0                       // GATES*KP*2        = 139264
#define OFF_XS   139264                  // 2*AG*KP*2         = 4352
#define OFF_WC   143616                  // GATES*16          = 8192
#define OFF_POS  151808                  // (MAXSTEPS+1)*AG*8 = 1344
#define OFF_SH   153152                  // AG*HID*4          = 4096
#define OFF_S1   157248                  // AG*64*4           = 2048
#define OFF_S2   159296                  // AG*32*4           = 1024
#define SMEM_TOTAL 160320

__device__ __forceinline__ float tanha(float x) {
    float y;
    asm("tanh.approx.f32 %0, %1;" : "=f"(y) : "f"(x));
    return y;
}
__device__ __forceinline__ float sigf(float x) {
    return fmaf(tanha(0.5f * x), 0.5f, 0.5f);
}

__device__ __forceinline__ void mma16816(float d[4], const uint32_t a[4],
                                         uint32_t b0, uint32_t b1) {
    asm volatile(
        "mma.sync.aligned.m16n8k16.row.col.f32.f16.f16.f32 "
        "{%0,%1,%2,%3},{%4,%5,%6,%7},{%8,%9},{%0,%1,%2,%3};"
        : "+f"(d[0]), "+f"(d[1]), "+f"(d[2]), "+f"(d[3])
        : "r"(a[0]), "r"(a[1]), "r"(a[2]), "r"(a[3]), "r"(b0), "r"(b1));
}

__global__ void __launch_bounds__(NTHR, 1) fused_kernel(
    const float* __restrict__ obs, const float* __restrict__ pred,
    const void*  __restrict__ bsplit,
    const float* __restrict__ W_emb, const float* __restrict__ b_emb,
    const float* __restrict__ W_ih,  const float* __restrict__ W_hh,
    const float* __restrict__ b_ih,  const float* __restrict__ b_hh,
    const float* __restrict__ W1, const float* __restrict__ b1,
    const float* __restrict__ W2, const float* __restrict__ b2,
    const float* __restrict__ W3, const float* __restrict__ b3,
    float* __restrict__ out,
    int N, int T_obs, int steps)
{
    extern __shared__ char smraw[];
    __half*  Ws    = (__half*) (smraw + OFF_WS);
    __half*  Xs    = (__half*) (smraw + OFF_XS);
    float4*  s_wc  = (float4*) (smraw + OFF_WC);
    float2*  s_pos = (float2*) (smraw + OFF_POS);
    float*   sh    = (float*)  (smraw + OFF_SH);
    float*   s1    = (float*)  (smraw + OFF_S1);
    float*   s2    = (float*)  (smraw + OFF_S2);
    __shared__ int s_agent[AG];

    const int tid  = threadIdx.x;
    const int w    = tid >> 5;           // 0..15
    const int lane = tid & 31;
    const int r    = lane >> 2;          // 0..7 : agent column / unit row
    const int q    = lane & 3;
    const int row0 = blockIdx.x * AG;
    const int u    = 8 * w + r;          // hidden unit owned by this thread

    // ---- prologue 1: W_hh fp32 -> f16 SMEM (pitched) ----
    for (int i = tid; i < GATES * HID / 4; i += NTHR) {
        float4 v = ((const float4*)W_hh)[i];
        int row = i >> 5;
        int c4  = (i & 31) << 2;
        __half* p = Ws + row * KP + c4;
        *(__half2*)(p)     = __floats2half2_rn(v.x, v.y);
        *(__half2*)(p + 2) = __floats2half2_rn(v.z, v.w);
    }

    // ---- prologue 2: fold input-side weights (1 gate / thread) ----
    {
        const int n = tid;   // NTHR == GATES
        float wc0 = 0.f, wc1 = 0.f, bc = 0.f;
        const float* wr = W_ih + (size_t)n * EMB;
        #pragma unroll 4
        for (int e = 0; e < EMB; e++) {
            float ww = wr[e];
            wc0 += ww * W_emb[2 * e + 0];
            wc1 += ww * W_emb[2 * e + 1];
            bc  += ww * b_emb[e];
        }
        s_wc[n] = make_float4(4.0f * wc0, 4.0f * wc1, bc + b_ih[n] + b_hh[n], 0.f);
    }

    // ---- prologue 3: agent indices + positions ----
    if (tid < AG) {
        int row = row0 + tid;
        const int* p32 = (const int*)bsplit;   // dtype-robust int32/int64
        int agent = (p32[NSEL] == N) ? p32[row]
                                     : (int)((const long long*)bsplit)[row];
        s_agent[tid] = agent;
    }
    __syncthreads();
    for (int i = tid; i < (steps + 1) * AG; i += NTHR) {
        int t = i / AG, al = i % AG;
        int agent = s_agent[al];
        const float* f = (t < T_obs)
            ? obs  + ((size_t)t * N + agent) * 2
            : pred + ((size_t)(t - T_obs) * N + agent) * 2;
        s_pos[i] = make_float2(f[0], f[1]);
    }

    // ---- prologue 4: zero h ping-pong ----
    for (int i = tid; i < 2 * AG * KP / 2; i += NTHR)
        ((uint32_t*)Xs)[i] = 0u;

    __syncthreads();

    // ---- hoist W fragments into registers: gates on M, k on K ----
    // tile0 rows: m<8 -> gate0 unit u ; m>=8 -> gate1 unit u
    // tile1 rows: gate2 / gate3.
    uint32_t A0[8][4], A1[8][4];
    {
        const __half* g0 = Ws + (0 * 128 + u) * KP;
        const __half* g1 = Ws + (1 * 128 + u) * KP;
        const __half* g2 = Ws + (2 * 128 + u) * KP;
        const __half* g3 = Ws + (3 * 128 + u) * KP;
        #pragma unroll
        for (int kc = 0; kc < 8; kc++) {
            const int k = kc * 16 + 2 * q;
            A0[kc][0] = *(const uint32_t*)(g0 + k);
            A0[kc][1] = *(const uint32_t*)(g1 + k);
            A0[kc][2] = *(const uint32_t*)(g0 + k + 8);
            A0[kc][3] = *(const uint32_t*)(g1 + k + 8);
            A1[kc][0] = *(const uint32_t*)(g2 + k);
            A1[kc][1] = *(const uint32_t*)(g3 + k);
            A1[kc][2] = *(const uint32_t*)(g2 + k + 8);
            A1[kc][3] = *(const uint32_t*)(g3 + k + 8);
        }
    }

    // ---- input-fold coefficients for this thread's 4 gate rows ----
    float wc0[4], wc1[4], bcr[4];
    #pragma unroll
    for (int g = 0; g < 4; g++) {
        float4 wc = s_wc[g * 128 + u];
        wc0[g] = wc.x; wc1[g] = wc.y; bcr[g] = wc.z;
    }

    // cell/hidden state for (agent 2q, u) and (agent 2q+1, u)
    float c0 = 0.f, c1 = 0.f, h0 = 0.f, h1 = 0.f;

    const int a0i = 2 * q, a1i = 2 * q + 1;

    // =========================== recurrence ===============================
    for (int t = 0; t < steps; t++) {
        const int cur = t & 1, nxt = cur ^ 1;
        __syncthreads();   // prev-step h STS visible

        // velocities + masks for this thread's two agents
        float2 pa0 = s_pos[t * AG + a0i];
        float2 pa1 = s_pos[(t + 1) * AG + a0i];
        float2 pb0 = s_pos[t * AG + a1i];
        float2 pb1 = s_pos[(t + 1) * AG + a1i];
        bool  m0 = !(isnan(pa0.x) || isnan(pa1.x));
        bool  m1 = !(isnan(pb0.x) || isnan(pb1.x));
        float vx0 = m0 ? (pa1.x - pa0.x) : 0.f, vy0 = m0 ? (pa1.y - pa0.y) : 0.f;
        float vx1 = m1 ? (pb1.x - pb0.x) : 0.f, vy1 = m1 ? (pb1.y - pb0.y) : 0.f;

        // accumulators seeded with on-the-fly input gates
        // d0: {gate0 a0, gate0 a1, gate1 a0, gate1 a1}; d1: gates 2,3
        float d0[4], d1[4];
        d0[0] = fmaf(vx0, wc0[0], fmaf(vy0, wc1[0], bcr[0]));
        d0[1] = fmaf(vx1, wc0[0], fmaf(vy1, wc1[0], bcr[0]));
        d0[2] = fmaf(vx0, wc0[1], fmaf(vy0, wc1[1], bcr[1]));
        d0[3] = fmaf(vx1, wc0[1], fmaf(vy1, wc1[1], bcr[1]));
        d1[0] = fmaf(vx0, wc0[2], fmaf(vy0, wc1[2], bcr[2]));
        d1[1] = fmaf(vx1, wc0[2], fmaf(vy1, wc1[2], bcr[2]));
        d1[2] = fmaf(vx0, wc0[3], fmaf(vy0, wc1[3], bcr[3]));
        d1[3] = fmaf(vx1, wc0[3], fmaf(vy1, wc1[3], bcr[3]));

        // gates += W_hh @ h^T : B = h[agent r][k], loaded per kc
        const __half* Xc = Xs + cur * AG * KP + r * KP;
        #pragma unroll
        for (int kc = 0; kc < 8; kc++) {
            const int k = kc * 16 + 2 * q;
            uint32_t b0 = *(const uint32_t*)(Xc + k);
            uint32_t b1 = *(const uint32_t*)(Xc + k + 8);
            mma16816(d0, A0[kc], b0, b1);
            mma16816(d1, A1[kc], b0, b1);
        }

        // epilogue: i=d_0, f=d_1gate, g, o ; update (agent,unit) pairs
        {
            float iv = sigf (d0[0]);
            float fv = sigf (d0[2]);
            float gv = tanha(d1[0]);
            float ov = sigf (d1[2]);
            float c2 = fmaf(fv, c0, iv * gv);
            float h2 = ov * tanha(c2);
            if (m0) { c0 = c2; h0 = h2; }
        }
        {
            float iv = sigf (d0[1]);
            float fv = sigf (d0[3]);
            float gv = tanha(d1[1]);
            float ov = sigf (d1[3]);
            float c2 = fmaf(fv, c1, iv * gv);
            float h2 = ov * tanha(c2);
            if (m1) { c1 = c2; h1 = h2; }
        }
        __half* Xn = Xs + nxt * AG * KP;
        Xn[a0i * KP + u] = __float2half_rn(h0);
        Xn[a1i * KP + u] = __float2half_rn(h1);
    }

    // =========================== fused MLP tail ===========================
    sh[a0i * HID + u] = h0;
    sh[a1i * HID + u] = h1;
    __syncthreads();

    // layer 1: (8 x 128) @ W1^T(64x128) -> relu -> s1[8][64]
    {
        const int u1 = tid & 63;
        const int a  = tid >> 6;            // 8 agents
        float acc = b1[u1];
        const float* wr = W1 + (size_t)u1 * HID;
        const float* hv = sh + a * HID;
        #pragma unroll 8
        for (int k = 0; k < HID; k += 4) {
            float4 wv = *(const float4*)(wr + k);
            float4 xv = *(const float4*)(hv + k);
            acc += wv.x * xv.x + wv.y * xv.y + wv.z * xv.z + wv.w * xv.w;
        }
        s1[a * 64 + u1] = fmaxf(acc, 0.f);
    }
    __syncthreads();

    // layer 2: (8 x 64) @ W2^T(32x64) -> relu -> s2[8][32]
    if (tid < 256) {
        const int u2 = tid & 31;
        const int a  = tid >> 5;
        float acc = b2[u2];
        const float* wr = W2 + (size_t)u2 * 64;
        const float* xv = s1 + a * 64;
        #pragma unroll 4
        for (int k = 0; k < 64; k += 4) {
            float4 wv = *(const float4*)(wr + k);
            float4 hv = *(const float4*)(xv + k);
            acc += wv.x * hv.x + wv.y * hv.y + wv.z * hv.z + wv.w * hv.w;
        }
        s2[a * 32 + u2] = fmaxf(acc, 0.f);
    }
    __syncthreads();

    // layer 3: (8 x 32) @ W3^T(1x32) -> relu -> out
    if (tid < AG) {
        float acc = b3[0];
        #pragma unroll
        for (int k = 0; k < 32; k++) acc += W3[k] * s2[tid * 32 + k];
        out[row0 + tid] = fmaxf(acc, 0.f);
    }
}

// ------------------------------- launcher ----------------------------------
extern "C" void kernel_launch(void* const* d_in, const int* in_sizes, int n_in,
                              void* d_out, int out_size) {
    const float* observed   = (const float*)d_in[0];
    const float* prediction = (const float*)d_in[1];
    const void*  bsplit     = d_in[3];
    const float* W_emb      = (const float*)d_in[4];
    const float* b_emb      = (const float*)d_in[5];
    const float* W_ih       = (const float*)d_in[6];
    const float* W_hh       = (const float*)d_in[7];
    const float* b_ih       = (const float*)d_in[8];
    const float* b_hh       = (const float*)d_in[9];
    const float* W1         = (const float*)d_in[10];
    const float* b1         = (const float*)d_in[11];
    const float* W2         = (const float*)d_in[12];
    const float* b2         = (const float*)d_in[13];
    const float* W3         = (const float*)d_in[14];
    const float* b3         = (const float*)d_in[15];
    float* out = (float*)d_out;

    const int N      = in_sizes[2] / 2;               // goals: (N,2)
    const int T_obs  = in_sizes[0] / (2 * N);
    const int T_pred = in_sizes[1] / (2 * N);
    int steps = T_obs + T_pred - 1;
    if (steps > MAXSTEPS) steps = MAXSTEPS;

    cudaFuncSetAttribute(fused_kernel, cudaFuncAttributeMaxDynamicSharedMemorySize,
                         SMEM_TOTAL);

    fused_kernel<<<NBLK, NTHR, SMEM_TOTAL>>>(
        observed, prediction, bsplit,
        W_emb, b_emb, W_ih, W_hh, b_ih, b_hh,
        W1, b1, W2, b2, W3, b3,
        out, N, T_obs, steps);
}

// round 5
// speedup vs baseline: 3.5295x; 1.8373x over previous
#include <cuda_runtime.h>
#include <cuda_fp16.h>
#include <cstdint>

// ---------------------------------------------------------------------------
// Fused LSTMDiscriminator, round 5: all row-consumed fp32 weights staged
// through SMEM with coalesced LDG + odd-pitch conflict-free LDS.
// MMA transposed (gates on M, agents on N); W_hh fully register-resident.
// ---------------------------------------------------------------------------

#define GATES    512
#define HID      128
#define EMB      64
#define NSEL     512
#define MAXSTEPS 20
#define AG       8           // agents per block (one n8 MMA tile)
#define KP       136         // W_hh pitch in halves
#define PIH      65          // W_ih staging pitch (floats)
#define PW1      129         // W1 staging pitch
#define PW2      65          // W2 staging pitch
#define NBLK     (NSEL/AG)   // 64 blocks
#define NTHR     512

#define OFF_WS   0                       // 139264: W_hh f16 / W_ih f32 (time-shared)
#define OFF_XS   139264                  // 4352 : h ping-pong
#define OFF_WC   143616                  // 8192 : folded coefs
#define OFF_POS  151808                  // 1344 : positions
#define OFF_SH   153152                  // 4096 : final h
#define OFF_S1   157248                  // 2048
#define OFF_S2   159296                  // 1024
#define OFF_W1S  160320                  // 33024: W1 pitch-129
#define OFF_W2S  193344                  // 8320 : W2 pitch-65
#define SMEM_TOTAL 201664

__device__ __forceinline__ float tanha(float x) {
    float y;
    asm("tanh.approx.f32 %0, %1;" : "=f"(y) : "f"(x));
    return y;
}
__device__ __forceinline__ float sigf(float x) {
    return fmaf(tanha(0.5f * x), 0.5f, 0.5f);
}

__device__ __forceinline__ void mma16816(float d[4], const uint32_t a[4],
                                         uint32_t b0, uint32_t b1) {
    asm volatile(
        "mma.sync.aligned.m16n8k16.row.col.f32.f16.f16.f32 "
        "{%0,%1,%2,%3},{%4,%5,%6,%7},{%8,%9},{%0,%1,%2,%3};"
        : "+f"(d[0]), "+f"(d[1]), "+f"(d[2]), "+f"(d[3])
        : "r"(a[0]), "r"(a[1]), "r"(a[2]), "r"(a[3]), "r"(b0), "r"(b1));
}

__global__ void __launch_bounds__(NTHR, 1) fused_kernel(
    const float* __restrict__ obs, const float* __restrict__ pred,
    const void*  __restrict__ bsplit,
    const float* __restrict__ W_emb, const float* __restrict__ b_emb,
    const float* __restrict__ W_ih,  const float* __restrict__ W_hh,
    const float* __restrict__ b_ih,  const float* __restrict__ b_hh,
    const float* __restrict__ W1, const float* __restrict__ b1,
    const float* __restrict__ W2, const float* __restrict__ b2,
    const float* __restrict__ W3, const float* __restrict__ b3,
    float* __restrict__ out,
    int N, int T_obs, int steps)
{
    extern __shared__ char smraw[];
    __half*  Ws    = (__half*) (smraw + OFF_WS);   // W_hh f16 (phase C+)
    float*   Wif   = (float*)  (smraw + OFF_WS);   // W_ih f32 (phase A/B)
    __half*  Xs    = (__half*) (smraw + OFF_XS);
    float4*  s_wc  = (float4*) (smraw + OFF_WC);
    float2*  s_pos = (float2*) (smraw + OFF_POS);
    float*   sh    = (float*)  (smraw + OFF_SH);
    float*   s1    = (float*)  (smraw + OFF_S1);
    float*   s2    = (float*)  (smraw + OFF_S2);
    float*   W1s   = (float*)  (smraw + OFF_W1S);
    float*   W2s   = (float*)  (smraw + OFF_W2S);
    __shared__ int s_agent[AG];

    const int tid  = threadIdx.x;
    const int w    = tid >> 5;
    const int lane = tid & 31;
    const int r    = lane >> 2;          // 0..7
    const int q    = lane & 3;
    const int row0 = blockIdx.x * AG;
    const int u    = 8 * w + r;          // hidden unit owned by this thread

    // ===== phase A: coalesced stage of W_ih (f32, pitch 65) + agent ids ====
    #pragma unroll
    for (int k = 0; k < 16; k++) {
        int i = tid + 512 * k;                 // float4 index (8192 total)
        float4 v = ((const float4*)W_ih)[i];
        int row = i >> 4;                      // 16 float4 per 64-float row
        int col = (i & 15) << 2;
        float* p = Wif + row * PIH + col;
        p[0] = v.x; p[1] = v.y; p[2] = v.z; p[3] = v.w;
    }
    if (tid < AG) {
        int row = row0 + tid;
        const int* p32 = (const int*)bsplit;   // dtype-robust int32/int64
        int agent = (p32[NSEL] == N) ? p32[row]
                                     : (int)((const long long*)bsplit)[row];
        s_agent[tid] = agent;
    }
    __syncthreads();

    // ===== phase B: fold input-side weights (conflict-free LDS) + pos =====
    {
        const int n = tid;                     // NTHR == GATES
        const float* wr = Wif + n * PIH;
        float wc0 = 0.f, wc1 = 0.f, bc = 0.f;
        #pragma unroll
        for (int e = 0; e < EMB; e++) {
            float  ww = wr[e];
            float2 we = ((const float2*)W_emb)[e];
            wc0 += ww * we.x;
            wc1 += ww * we.y;
            bc  += ww * b_emb[e];
        }
        s_wc[n] = make_float4(4.0f * wc0, 4.0f * wc1, bc + b_ih[n] + b_hh[n], 0.f);
    }
    for (int i = tid; i < (steps + 1) * AG; i += NTHR) {
        int t = i / AG, al = i % AG;
        int agent = s_agent[al];
        const float* f = (t < T_obs)
            ? obs  + ((size_t)t * N + agent) * 2
            : pred + ((size_t)(t - T_obs) * N + agent) * 2;
        s_pos[i] = make_float2(f[0], f[1]);
    }
    __syncthreads();   // fold reads of Wif complete before overwrite

    // ===== phase C: stage W_hh f16 (overwrites Wif), W1, W2; zero Xs ======
    for (int i = tid; i < GATES * HID / 4; i += NTHR) {
        float4 v = ((const float4*)W_hh)[i];
        int row = i >> 5;
        int c4  = (i & 31) << 2;
        __half* p = Ws + row * KP + c4;
        *(__half2*)(p)     = __floats2half2_rn(v.x, v.y);
        *(__half2*)(p + 2) = __floats2half2_rn(v.z, v.w);
    }
    #pragma unroll
    for (int k = 0; k < 4; k++) {
        int i = tid + 512 * k;                 // float4 index (2048 total)
        float4 v = ((const float4*)W1)[i];
        int row = i >> 5;                      // 32 float4 per 128-float row
        int col = (i & 31) << 2;
        float* p = W1s + row * PW1 + col;
        p[0] = v.x; p[1] = v.y; p[2] = v.z; p[3] = v.w;
    }
    {
        int i = tid;                           // 512 float4 (32x64)
        float4 v = ((const float4*)W2)[i];
        int row = i >> 4;                      // 16 float4 per 64-float row
        int col = (i & 15) << 2;
        float* p = W2s + row * PW2 + col;
        p[0] = v.x; p[1] = v.y; p[2] = v.z; p[3] = v.w;
    }
    for (int i = tid; i < 2 * AG * KP / 2; i += NTHR)
        ((uint32_t*)Xs)[i] = 0u;
    __syncthreads();

    // ===== phase D: hoist W_hh fragments + fold coefs into registers ======
    uint32_t A0[8][4], A1[8][4];
    {
        const __half* g0 = Ws + (0 * 128 + u) * KP;
        const __half* g1 = Ws + (1 * 128 + u) * KP;
        const __half* g2 = Ws + (2 * 128 + u) * KP;
        const __half* g3 = Ws + (3 * 128 + u) * KP;
        #pragma unroll
        for (int kc = 0; kc < 8; kc++) {
            const int k = kc * 16 + 2 * q;
            A0[kc][0] = *(const uint32_t*)(g0 + k);
            A0[kc][1] = *(const uint32_t*)(g1 + k);
            A0[kc][2] = *(const uint32_t*)(g0 + k + 8);
            A0[kc][3] = *(const uint32_t*)(g1 + k + 8);
            A1[kc][0] = *(const uint32_t*)(g2 + k);
            A1[kc][1] = *(const uint32_t*)(g3 + k);
            A1[kc][2] = *(const uint32_t*)(g2 + k + 8);
            A1[kc][3] = *(const uint32_t*)(g3 + k + 8);
        }
    }
    float wc0[4], wc1[4], bcr[4];
    #pragma unroll
    for (int g = 0; g < 4; g++) {
        float4 wc = s_wc[g * 128 + u];
        wc0[g] = wc.x; wc1[g] = wc.y; bcr[g] = wc.z;
    }

    float c0 = 0.f, c1 = 0.f, h0 = 0.f, h1 = 0.f;
    const int a0i = 2 * q, a1i = 2 * q + 1;

    // =========================== recurrence ===============================
    for (int t = 0; t < steps; t++) {
        const int cur = t & 1, nxt = cur ^ 1;

        // static-data work before the barrier (overlaps stragglers)
        float2 pa0 = s_pos[t * AG + a0i];
        float2 pa1 = s_pos[(t + 1) * AG + a0i];
        float2 pb0 = s_pos[t * AG + a1i];
        float2 pb1 = s_pos[(t + 1) * AG + a1i];
        bool  m0 = !(isnan(pa0.x) || isnan(pa1.x));
        bool  m1 = !(isnan(pb0.x) || isnan(pb1.x));
        float vx0 = m0 ? (pa1.x - pa0.x) : 0.f, vy0 = m0 ? (pa1.y - pa0.y) : 0.f;
        float vx1 = m1 ? (pb1.x - pb0.x) : 0.f, vy1 = m1 ? (pb1.y - pb0.y) : 0.f;

        // split accumulators: a-chain seeded with input gates, b-chain zero
        float d0a[4], d0b[4], d1a[4], d1b[4];
        d0a[0] = fmaf(vx0, wc0[0], fmaf(vy0, wc1[0], bcr[0]));
        d0a[1] = fmaf(vx1, wc0[0], fmaf(vy1, wc1[0], bcr[0]));
        d0a[2] = fmaf(vx0, wc0[1], fmaf(vy0, wc1[1], bcr[1]));
        d0a[3] = fmaf(vx1, wc0[1], fmaf(vy1, wc1[1], bcr[1]));
        d1a[0] = fmaf(vx0, wc0[2], fmaf(vy0, wc1[2], bcr[2]));
        d1a[1] = fmaf(vx1, wc0[2], fmaf(vy1, wc1[2], bcr[2]));
        d1a[2] = fmaf(vx0, wc0[3], fmaf(vy0, wc1[3], bcr[3]));
        d1a[3] = fmaf(vx1, wc0[3], fmaf(vy1, wc1[3], bcr[3]));
        #pragma unroll
        for (int i = 0; i < 4; i++) { d0b[i] = 0.f; d1b[i] = 0.f; }

        __syncthreads();   // h(t) STS from previous step visible

        const __half* Xc = Xs + cur * AG * KP + r * KP;
        #pragma unroll
        for (int kc = 0; kc < 8; kc += 2) {
            const int k0 = kc * 16 + 2 * q;
            uint32_t b0 = *(const uint32_t*)(Xc + k0);
            uint32_t b1 = *(const uint32_t*)(Xc + k0 + 8);
            mma16816(d0a, A0[kc], b0, b1);
            mma16816(d1a, A1[kc], b0, b1);
            const int k1 = k0 + 16;
            uint32_t b2 = *(const uint32_t*)(Xc + k1);
            uint32_t b3 = *(const uint32_t*)(Xc + k1 + 8);
            mma16816(d0b, A0[kc + 1], b2, b3);
            mma16816(d1b, A1[kc + 1], b2, b3);
        }
        float d0[4], d1[4];
        #pragma unroll
        for (int i = 0; i < 4; i++) { d0[i] = d0a[i] + d0b[i]; d1[i] = d1a[i] + d1b[i]; }

        // epilogue: this thread owns (agent a0i,u) and (agent a1i,u)
        {
            float iv = sigf (d0[0]);
            float fv = sigf (d0[2]);
            float gv = tanha(d1[0]);
            float ov = sigf (d1[2]);
            float c2 = fmaf(fv, c0, iv * gv);
            float h2 = ov * tanha(c2);
            if (m0) { c0 = c2; h0 = h2; }
        }
        {
            float iv = sigf (d0[1]);
            float fv = sigf (d0[3]);
            float gv = tanha(d1[1]);
            float ov = sigf (d1[3]);
            float c2 = fmaf(fv, c1, iv * gv);
            float h2 = ov * tanha(c2);
            if (m1) { c1 = c2; h1 = h2; }
        }
        __half* Xn = Xs + nxt * AG * KP;
        Xn[a0i * KP + u] = __float2half_rn(h0);
        Xn[a1i * KP + u] = __float2half_rn(h1);
    }

    // =========================== fused MLP tail ===========================
    sh[a0i * HID + u] = h0;
    sh[a1i * HID + u] = h1;
    __syncthreads();

    // layer 1: (8 x 128) @ W1^T -> relu ; conflict-free pitched LDS
    {
        const int u1 = tid & 63;
        const int a  = tid >> 6;
        float acc = b1[u1];
        const float* wr = W1s + u1 * PW1;
        const float* hv = sh + a * HID;
        #pragma unroll
        for (int k = 0; k < HID; k++) acc = fmaf(wr[k], hv[k], acc);
        s1[a * 64 + u1] = fmaxf(acc, 0.f);
    }
    __syncthreads();

    // layer 2: (8 x 64) @ W2^T -> relu
    if (tid < 256) {
        const int u2 = tid & 31;
        const int a  = tid >> 5;
        float acc = b2[u2];
        const float* wr = W2s + u2 * PW2;
        const float* xv = s1 + a * 64;
        #pragma unroll
        for (int k = 0; k < 64; k++) acc = fmaf(wr[k], xv[k], acc);
        s2[a * 32 + u2] = fmaxf(acc, 0.f);
    }
    __syncthreads();

    // layer 3: (8 x 32) @ W3^T -> relu -> out
    if (tid < AG) {
        float acc = b3[0];
        #pragma unroll
        for (int k = 0; k < 32; k++) acc += W3[k] * s2[tid * 32 + k];
        out[row0 + tid] = fmaxf(acc, 0.f);
    }
}

// ------------------------------- launcher ----------------------------------
extern "C" void kernel_launch(void* const* d_in, const int* in_sizes, int n_in,
                              void* d_out, int out_size) {
    const float* observed   = (const float*)d_in[0];
    const float* prediction = (const float*)d_in[1];
    const void*  bsplit     = d_in[3];
    const float* W_emb      = (const float*)d_in[4];
    const float* b_emb      = (const float*)d_in[5];
    const float* W_ih       = (const float*)d_in[6];
    const float* W_hh       = (const float*)d_in[7];
    const float* b_ih       = (const float*)d_in[8];
    const float* b_hh       = (const float*)d_in[9];
    const float* W1         = (const float*)d_in[10];
    const float* b1         = (const float*)d_in[11];
    const float* W2         = (const float*)d_in[12];
    const float* b2         = (const float*)d_in[13];
    const float* W3         = (const float*)d_in[14];
    const float* b3         = (const float*)d_in[15];
    float* out = (float*)d_out;

    const int N      = in_sizes[2] / 2;               // goals: (N,2)
    const int T_obs  = in_sizes[0] / (2 * N);
    const int T_pred = in_sizes[1] / (2 * N);
    int steps = T_obs + T_pred - 1;
    if (steps > MAXSTEPS) steps = MAXSTEPS;

    cudaFuncSetAttribute(fused_kernel, cudaFuncAttributeMaxDynamicSharedMemorySize,
                         SMEM_TOTAL);

    fused_kernel<<<NBLK, NTHR, SMEM_TOTAL>>>(
        observed, prediction, bsplit,
        W_emb, b_emb, W_ih, W_hh, b_ih, b_hh,
        W1, b1, W2, b2, W3, b3,
        out, N, T_obs, steps);
}

// round 6
// speedup vs baseline: 3.7790x; 1.0707x over previous
#include <cuda_runtime.h>
#include <cuda_fp16.h>
#include <cstdint>

// ---------------------------------------------------------------------------
// Fused LSTMDiscriminator, round 6:
//  - h buffer transposed to [unit][agent] -> B frags via ldmatrix.x4.trans
//    (4 LDSM vs 16 LDS per warp per step), packed single STS.32 h store
//  - velocity/mask tables precomputed in prologue (loop: 1 LDS.128 + 1 LDS.64)
//  - vectorized input-weight fold
// W_hh fully register-resident as MMA A-fragments (gates on M, agents on N).
// ---------------------------------------------------------------------------

#define GATES    512
#define HID      128
#define EMB      64
#define NSEL     512
#define MAXSTEPS 20
#define AG       8
#define KP       136         // W_hh f16 staging pitch (halves)
#define PIH      66          // W_ih f32 staging pitch (floats)
#define PW1      129
#define PW2      65
#define NBLK     (NSEL/AG)   // 64 blocks
#define NTHR     512

// SMEM layout (bytes, 16B aligned)
#define OFF_WS   0                        // 139264 : W_hh f16 / W_ih f32 (time-shared)
#define OFF_XS   139264                   // 4096   : h ping-pong [2][128 units][8 agents] f16
#define OFF_VEL  143360                   // 1280   : vel float2[20][8]
#define OFF_MSK  144640                   // 640    : mask float[20][8]
#define OFF_WC   145280                   // 8192   : folded coefs float4[512]
#define OFF_WE   153472                   // 512    : W_emb float2[64]
#define OFF_BE   153984                   // 256    : b_emb
#define OFF_SH   154496                   // 4096   : final h fp32
#define OFF_S1   158592                   // 2048
#define OFF_S2   160640                   // 1024
#define OFF_W1S  161664                   // 33024  : W1 pitch-129
#define OFF_W2S  194688                   // 8320   : W2 pitch-65
#define SMEM_TOTAL 203008

__device__ __forceinline__ float tanha(float x) {
    float y;
    asm("tanh.approx.f32 %0, %1;" : "=f"(y) : "f"(x));
    return y;
}
__device__ __forceinline__ float sigf(float x) {
    return fmaf(tanha(0.5f * x), 0.5f, 0.5f);
}

__device__ __forceinline__ void mma16816(float d[4], const uint32_t a[4],
                                         uint32_t b0, uint32_t b1) {
    asm volatile(
        "mma.sync.aligned.m16n8k16.row.col.f32.f16.f16.f32 "
        "{%0,%1,%2,%3},{%4,%5,%6,%7},{%8,%9},{%0,%1,%2,%3};"
        : "+f"(d[0]), "+f"(d[1]), "+f"(d[2]), "+f"(d[3])
        : "r"(a[0]), "r"(a[1]), "r"(a[2]), "r"(a[3]), "r"(b0), "r"(b1));
}

__global__ void __launch_bounds__(NTHR, 1) fused_kernel(
    const float* __restrict__ obs, const float* __restrict__ pred,
    const void*  __restrict__ bsplit,
    const float* __restrict__ W_emb, const float* __restrict__ b_emb,
    const float* __restrict__ W_ih,  const float* __restrict__ W_hh,
    const float* __restrict__ b_ih,  const float* __restrict__ b_hh,
    const float* __restrict__ W1, const float* __restrict__ b1,
    const float* __restrict__ W2, const float* __restrict__ b2,
    const float* __restrict__ W3, const float* __restrict__ b3,
    float* __restrict__ out,
    int N, int T_obs, int steps)
{
    extern __shared__ char smraw[];
    __half*  Ws    = (__half*) (smraw + OFF_WS);
    float*   Wif   = (float*)  (smraw + OFF_WS);
    __half*  Xs    = (__half*) (smraw + OFF_XS);   // [2][128][8]
    float2*  s_vel = (float2*) (smraw + OFF_VEL);  // [t][agent]
    float*   s_msk = (float*)  (smraw + OFF_MSK);  // [t][agent]
    float4*  s_wc  = (float4*) (smraw + OFF_WC);
    float2*  s_we  = (float2*) (smraw + OFF_WE);
    float*   s_be  = (float*)  (smraw + OFF_BE);
    float*   sh    = (float*)  (smraw + OFF_SH);
    float*   s1    = (float*)  (smraw + OFF_S1);
    float*   s2    = (float*)  (smraw + OFF_S2);
    float*   W1s   = (float*)  (smraw + OFF_W1S);
    float*   W2s   = (float*)  (smraw + OFF_W2S);
    __shared__ int s_agent[AG];

    const int tid  = threadIdx.x;
    const int w    = tid >> 5;
    const int lane = tid & 31;
    const int r    = lane >> 2;
    const int q    = lane & 3;
    const int row0 = blockIdx.x * AG;
    const int u    = 8 * w + r;          // hidden unit owned by this thread

    // ===== phase A: stage W_ih (pitch 66), W_emb, b_emb; agent ids =========
    #pragma unroll
    for (int k = 0; k < 16; k++) {
        int i = tid + 512 * k;                 // float4 idx over 512x64
        float4 v = ((const float4*)W_ih)[i];
        int row = i >> 4;
        int col = (i & 15) << 2;
        float* p = Wif + row * PIH + col;
        *(float2*)(p)     = make_float2(v.x, v.y);
        *(float2*)(p + 2) = make_float2(v.z, v.w);
    }
    if (tid < 32) ((float4*)s_we)[tid] = ((const float4*)W_emb)[tid];
    else if (tid < 48) ((float4*)s_be)[tid - 32] = ((const float4*)b_emb)[tid - 32];
    else if (tid >= 64 && tid < 64 + AG) {
        int row = row0 + (tid - 64);
        const int* p32 = (const int*)bsplit;   // dtype-robust int32/int64
        int agent = (p32[NSEL] == N) ? p32[row]
                                     : (int)((const long long*)bsplit)[row];
        s_agent[tid - 64] = agent;
    }
    __syncthreads();

    // ===== phase B: fold input weights; vel/mask tables ====================
    {
        const int n = tid;                     // NTHR == GATES
        const float2* wr = (const float2*)(Wif + n * PIH);
        float wc0 = 0.f, wc1 = 0.f, bc = 0.f;
        #pragma unroll
        for (int e2 = 0; e2 < EMB / 2; e2++) {
            float2 ww  = wr[e2];
            float2 wea = s_we[2 * e2];
            float2 web = s_we[2 * e2 + 1];
            float2 be  = ((const float2*)s_be)[e2];
            wc0 = fmaf(ww.x, wea.x, fmaf(ww.y, web.x, wc0));
            wc1 = fmaf(ww.x, wea.y, fmaf(ww.y, web.y, wc1));
            bc  = fmaf(ww.x, be.x,  fmaf(ww.y, be.y,  bc));
        }
        s_wc[n] = make_float4(4.0f * wc0, 4.0f * wc1, bc + b_ih[n] + b_hh[n], 0.f);
    }
    for (int i = tid; i < steps * AG; i += NTHR) {
        int t = i >> 3, a = i & 7;
        int agent = s_agent[a];
        const float* f0 = (t < T_obs)
            ? obs  + ((size_t)t * N + agent) * 2
            : pred + ((size_t)(t - T_obs) * N + agent) * 2;
        int t1 = t + 1;
        const float* f1 = (t1 < T_obs)
            ? obs  + ((size_t)t1 * N + agent) * 2
            : pred + ((size_t)(t1 - T_obs) * N + agent) * 2;
        float x0 = f0[0], y0 = f0[1], x1 = f1[0], y1 = f1[1];
        bool m = !(isnan(x0) || isnan(x1));
        s_vel[i] = make_float2(m ? (x1 - x0) : 0.f, m ? (y1 - y0) : 0.f);
        s_msk[i] = m ? 1.f : 0.f;
    }
    __syncthreads();   // Wif reads complete before W_hh overwrite

    // ===== phase C: stage W_hh f16, W1, W2; zero Xs buf0 ====================
    for (int i = tid; i < GATES * HID / 4; i += NTHR) {
        float4 v = ((const float4*)W_hh)[i];
        int row = i >> 5;
        int c4  = (i & 31) << 2;
        __half* p = Ws + row * KP + c4;
        *(__half2*)(p)     = __floats2half2_rn(v.x, v.y);
        *(__half2*)(p + 2) = __floats2half2_rn(v.z, v.w);
    }
    #pragma unroll
    for (int k = 0; k < 4; k++) {
        int i = tid + 512 * k;
        float4 v = ((const float4*)W1)[i];
        int row = i >> 5;
        int col = (i & 31) << 2;
        float* p = W1s + row * PW1 + col;
        p[0] = v.x; p[1] = v.y; p[2] = v.z; p[3] = v.w;
    }
    {
        int i = tid;
        float4 v = ((const float4*)W2)[i];
        int row = i >> 4;
        int col = (i & 15) << 2;
        float* p = W2s + row * PW2 + col;
        p[0] = v.x; p[1] = v.y; p[2] = v.z; p[3] = v.w;
    }
    ((uint32_t*)Xs)[tid] = 0u;    // zero buffer 0 (2048 B)
    __syncthreads();

    // ===== phase D: hoist A fragments (W_hh) + fold coefs ==================
    uint32_t A0[8][4], A1[8][4];
    {
        const __half* g0 = Ws + (0 * 128 + u) * KP;
        const __half* g1 = Ws + (1 * 128 + u) * KP;
        const __half* g2 = Ws + (2 * 128 + u) * KP;
        const __half* g3 = Ws + (3 * 128 + u) * KP;
        #pragma unroll
        for (int kc = 0; kc < 8; kc++) {
            const int k = kc * 16 + 2 * q;
            A0[kc][0] = *(const uint32_t*)(g0 + k);
            A0[kc][1] = *(const uint32_t*)(g1 + k);
            A0[kc][2] = *(const uint32_t*)(g0 + k + 8);
            A0[kc][3] = *(const uint32_t*)(g1 + k + 8);
            A1[kc][0] = *(const uint32_t*)(g2 + k);
            A1[kc][1] = *(const uint32_t*)(g3 + k);
            A1[kc][2] = *(const uint32_t*)(g2 + k + 8);
            A1[kc][3] = *(const uint32_t*)(g3 + k + 8);
        }
    }
    float wc0[4], wc1[4], bcr[4];
    #pragma unroll
    for (int g = 0; g < 4; g++) {
        float4 wc = s_wc[g * 128 + u];
        wc0[g] = wc.x; wc1[g] = wc.y; bcr[g] = wc.z;
    }

    float c0 = 0.f, c1 = 0.f, h0 = 0.f, h1 = 0.f;

    // SMEM raw addresses for LDSM / STS (Xs: [buf][unit][agent] halves)
    const uint32_t xs_base = (uint32_t)__cvta_generic_to_shared(Xs);
    const uint32_t ldm_off = xs_base + lane * 16;           // lane j -> unit row j
    const uint32_t sts_off = xs_base + u * 16 + q * 4;      // packed h2 store

    // =========================== recurrence ===============================
    for (int t = 0; t < steps; t++) {
        const int cur = t & 1, nxt = cur ^ 1;

        // vel + mask for this thread's agent pair (static tables)
        float4 v4 = *(const float4*)(s_vel + t * AG + 2 * q);
        float2 m2 = *(const float2*)(s_msk + t * AG + 2 * q);
        const bool m0 = (m2.x != 0.f), m1 = (m2.y != 0.f);

        // seed accumulators with input gates
        float d0a[4], d0b[4], d1a[4], d1b[4];
        d0a[0] = fmaf(v4.x, wc0[0], fmaf(v4.y, wc1[0], bcr[0]));
        d0a[1] = fmaf(v4.z, wc0[0], fmaf(v4.w, wc1[0], bcr[0]));
        d0a[2] = fmaf(v4.x, wc0[1], fmaf(v4.y, wc1[1], bcr[1]));
        d0a[3] = fmaf(v4.z, wc0[1], fmaf(v4.w, wc1[1], bcr[1]));
        d1a[0] = fmaf(v4.x, wc0[2], fmaf(v4.y, wc1[2], bcr[2]));
        d1a[1] = fmaf(v4.z, wc0[2], fmaf(v4.w, wc1[2], bcr[2]));
        d1a[2] = fmaf(v4.x, wc0[3], fmaf(v4.y, wc1[3], bcr[3]));
        d1a[3] = fmaf(v4.z, wc0[3], fmaf(v4.w, wc1[3], bcr[3]));
        #pragma unroll
        for (int i = 0; i < 4; i++) { d0b[i] = 0.f; d1b[i] = 0.f; }

        __syncthreads();   // h(t) stores visible

        // B frags via ldmatrix: chunk c covers kc=2c (m0,m1) and kc=2c+1 (m2,m3)
        const uint32_t xc = ldm_off + cur * 2048;
        #pragma unroll
        for (int cch = 0; cch < 4; cch++) {
            uint32_t b0a, b1a, b0b, b1b;
            asm volatile(
                "ldmatrix.sync.aligned.m8n8.x4.trans.shared.b16 "
                "{%0,%1,%2,%3}, [%4];"
                : "=r"(b0a), "=r"(b1a), "=r"(b0b), "=r"(b1b)
                : "r"(xc + cch * 512));
            mma16816(d0a, A0[2 * cch],     b0a, b1a);
            mma16816(d1a, A1[2 * cch],     b0a, b1a);
            mma16816(d0b, A0[2 * cch + 1], b0b, b1b);
            mma16816(d1b, A1[2 * cch + 1], b0b, b1b);
        }
        float d0[4], d1[4];
        #pragma unroll
        for (int i = 0; i < 4; i++) { d0[i] = d0a[i] + d0b[i]; d1[i] = d1a[i] + d1b[i]; }

        // epilogue: two cells (agents 2q, 2q+1; unit u)
        {
            float iv = sigf (d0[0]);
            float fv = sigf (d0[2]);
            float gv = tanha(d1[0]);
            float ov = sigf (d1[2]);
            float c2 = fmaf(fv, c0, iv * gv);
            float h2 = ov * tanha(c2);
            if (m0) { c0 = c2; h0 = h2; }
        }
        {
            float iv = sigf (d0[1]);
            float fv = sigf (d0[3]);
            float gv = tanha(d1[1]);
            float ov = sigf (d1[3]);
            float c2 = fmaf(fv, c1, iv * gv);
            float h2 = ov * tanha(c2);
            if (m1) { c1 = c2; h1 = h2; }
        }
        // packed h store: Xs[nxt][u][2q..2q+1]
        {
            __half2 hp = __floats2half2_rn(h0, h1);
            uint32_t hv = *(uint32_t*)&hp;
            asm volatile("st.shared.b32 [%0], %1;"
                         :: "r"(sts_off + nxt * 2048), "r"(hv));
        }
    }

    // =========================== fused MLP tail ===========================
    sh[(2 * q)     * HID + u] = h0;
    sh[(2 * q + 1) * HID + u] = h1;
    __syncthreads();

    // layer 1: (8 x 128) @ W1^T -> relu
    {
        const int u1 = tid & 63;
        const int a  = tid >> 6;
        float acc = b1[u1];
        const float* wr = W1s + u1 * PW1;
        const float* hv = sh + a * HID;
        #pragma unroll
        for (int k = 0; k < HID; k++) acc = fmaf(wr[k], hv[k], acc);
        s1[a * 64 + u1] = fmaxf(acc, 0.f);
    }
    __syncthreads();

    // layer 2: (8 x 64) @ W2^T -> relu
    if (tid < 256) {
        const int u2 = tid & 31;
        const int a  = tid >> 5;
        float acc = b2[u2];
        const float* wr = W2s + u2 * PW2;
        const float* xv = s1 + a * 64;
        #pragma unroll
        for (int k = 0; k < 64; k++) acc = fmaf(wr[k], xv[k], acc);
        s2[a * 32 + u2] = fmaxf(acc, 0.f);
    }
    __syncthreads();

    // layer 3
    if (tid < AG) {
        float acc = b3[0];
        #pragma unroll
        for (int k = 0; k < 32; k++) acc += W3[k] * s2[tid * 32 + k];
        out[row0 + tid] = fmaxf(acc, 0.f);
    }
}

// ------------------------------- launcher ----------------------------------
extern "C" void kernel_launch(void* const* d_in, const int* in_sizes, int n_in,
                              void* d_out, int out_size) {
    const float* observed   = (const float*)d_in[0];
    const float* prediction = (const float*)d_in[1];
    const void*  bsplit     = d_in[3];
    const float* W_emb      = (const float*)d_in[4];
    const float* b_emb      = (const float*)d_in[5];
    const float* W_ih       = (const float*)d_in[6];
    const float* W_hh       = (const float*)d_in[7];
    const float* b_ih       = (const float*)d_in[8];
    const float* b_hh       = (const float*)d_in[9];
    const float* W1         = (const float*)d_in[10];
    const float* b1         = (const float*)d_in[11];
    const float* W2         = (const float*)d_in[12];
    const float* b2         = (const float*)d_in[13];
    const float* W3         = (const float*)d_in[14];
    const float* b3         = (const float*)d_in[15];
    float* out = (float*)d_out;

    const int N      = in_sizes[2] / 2;               // goals: (N,2)
    const int T_obs  = in_sizes[0] / (2 * N);
    const int T_pred = in_sizes[1] / (2 * N);
    int steps = T_obs + T_pred - 1;
    if (steps > MAXSTEPS) steps = MAXSTEPS;

    cudaFuncSetAttribute(fused_kernel, cudaFuncAttributeMaxDynamicSharedMemorySize,
                         SMEM_TOTAL);

    fused_kernel<<<NBLK, NTHR, SMEM_TOTAL>>>(
        observed, prediction, bsplit,
        W_emb, b_emb, W_ih, W_hh, b_ih, b_hh,
        W1, b1, W2, b2, W3, b3,
        out, N, T_obs, steps);
}

// round 7
// speedup vs baseline: 4.1569x; 1.1000x over previous
#include <cuda_runtime.h>
#include <cuda_fp16.h>
#include <cstdint>

// ---------------------------------------------------------------------------
// Fused LSTMDiscriminator, round 7: AG=4 agents/block -> 128 blocks (more SMs,
// half per-thread epilogue/MUFU work). One LSTM cell per thread.
// Agents live in even MMA columns; odd columns stay zero.
// W_hh fully register-resident as MMA A-fragments (gates on M, agents on N).
// ---------------------------------------------------------------------------

#define GATES    512
#define HID      128
#define EMB      64
#define NSEL     512
#define MAXSTEPS 20
#define AG       4
#define KP       136         // W_hh f16 staging pitch (halves)
#define PIH      66          // W_ih f32 staging pitch (floats)
#define PW1      129
#define PW2      65
#define NBLK     (NSEL/AG)   // 128 blocks
#define NTHR     512

// SMEM layout (bytes, 16B aligned)
#define OFF_WS   0                        // 139264 : W_hh f16 / W_ih f32 (time-shared)
#define OFF_XS   139264                   // 4096   : h ping-pong [2][128 units][8 cols] f16
#define OFF_VEL  143360                   // 640    : vel float2[20][4]
#define OFF_MSK  144000                   // 320    : mask float[20][4]
#define OFF_WC   144384                   // 8192   : folded coefs float4[512]
#define OFF_WE   152576                   // 512    : W_emb float2[64]
#define OFF_BE   153088                   // 256    : b_emb
#define OFF_SH   153344                   // 2048   : final h fp32 [4][128]
#define OFF_S1   155392                   // 1024   : [4][64]
#define OFF_S2   156416                   // 512    : [4][32]
#define OFF_W1S  156928                   // 33024  : W1 pitch-129
#define OFF_W2S  189952                   // 8320   : W2 pitch-65
#define SMEM_TOTAL 198272

__device__ __forceinline__ float tanha(float x) {
    float y;
    asm("tanh.approx.f32 %0, %1;" : "=f"(y) : "f"(x));
    return y;
}
__device__ __forceinline__ float sigf(float x) {
    return fmaf(tanha(0.5f * x), 0.5f, 0.5f);
}

__device__ __forceinline__ void mma16816(float d[4], const uint32_t a[4],
                                         uint32_t b0, uint32_t b1) {
    asm volatile(
        "mma.sync.aligned.m16n8k16.row.col.f32.f16.f16.f32 "
        "{%0,%1,%2,%3},{%4,%5,%6,%7},{%8,%9},{%0,%1,%2,%3};"
        : "+f"(d[0]), "+f"(d[1]), "+f"(d[2]), "+f"(d[3])
        : "r"(a[0]), "r"(a[1]), "r"(a[2]), "r"(a[3]), "r"(b0), "r"(b1));
}

__global__ void __launch_bounds__(NTHR, 1) fused_kernel(
    const float* __restrict__ obs, const float* __restrict__ pred,
    const void*  __restrict__ bsplit,
    const float* __restrict__ W_emb, const float* __restrict__ b_emb,
    const float* __restrict__ W_ih,  const float* __restrict__ W_hh,
    const float* __restrict__ b_ih,  const float* __restrict__ b_hh,
    const float* __restrict__ W1, const float* __restrict__ b1,
    const float* __restrict__ W2, const float* __restrict__ b2,
    const float* __restrict__ W3, const float* __restrict__ b3,
    float* __restrict__ out,
    int N, int T_obs, int steps)
{
    extern __shared__ char smraw[];
    __half*  Ws    = (__half*) (smraw + OFF_WS);
    float*   Wif   = (float*)  (smraw + OFF_WS);
    __half*  Xs    = (__half*) (smraw + OFF_XS);   // [2][128][8]
    float2*  s_vel = (float2*) (smraw + OFF_VEL);  // [t][agent]
    float*   s_msk = (float*)  (smraw + OFF_MSK);  // [t][agent]
    float4*  s_wc  = (float4*) (smraw + OFF_WC);
    float2*  s_we  = (float2*) (smraw + OFF_WE);
    float*   s_be  = (float*)  (smraw + OFF_BE);
    float*   sh    = (float*)  (smraw + OFF_SH);
    float*   s1    = (float*)  (smraw + OFF_S1);
    float*   s2    = (float*)  (smraw + OFF_S2);
    float*   W1s   = (float*)  (smraw + OFF_W1S);
    float*   W2s   = (float*)  (smraw + OFF_W2S);
    __shared__ int s_agent[AG];

    const int tid  = threadIdx.x;
    const int w    = tid >> 5;
    const int lane = tid & 31;
    const int r    = lane >> 2;
    const int q    = lane & 3;           // agent owned by this thread
    const int row0 = blockIdx.x * AG;
    const int u    = 8 * w + r;          // hidden unit owned by this thread

    // ===== phase A: stage W_ih (pitch 66), W_emb, b_emb; agent ids =========
    #pragma unroll
    for (int k = 0; k < 16; k++) {
        int i = tid + 512 * k;                 // float4 idx over 512x64
        float4 v = ((const float4*)W_ih)[i];
        int row = i >> 4;
        int col = (i & 15) << 2;
        float* p = Wif + row * PIH + col;
        *(float2*)(p)     = make_float2(v.x, v.y);
        *(float2*)(p + 2) = make_float2(v.z, v.w);
    }
    if (tid < 32) ((float4*)s_we)[tid] = ((const float4*)W_emb)[tid];
    else if (tid < 48) ((float4*)s_be)[tid - 32] = ((const float4*)b_emb)[tid - 32];
    else if (tid >= 64 && tid < 64 + AG) {
        int row = row0 + (tid - 64);
        const int* p32 = (const int*)bsplit;   // dtype-robust int32/int64
        int agent = (p32[NSEL] == N) ? p32[row]
                                     : (int)((const long long*)bsplit)[row];
        s_agent[tid - 64] = agent;
    }
    __syncthreads();

    // ===== phase B: fold input weights; vel/mask tables ====================
    {
        const int n = tid;                     // NTHR == GATES
        const float2* wr = (const float2*)(Wif + n * PIH);
        float wc0 = 0.f, wc1 = 0.f, bc = 0.f;
        #pragma unroll
        for (int e2 = 0; e2 < EMB / 2; e2++) {
            float2 ww  = wr[e2];
            float2 wea = s_we[2 * e2];
            float2 web = s_we[2 * e2 + 1];
            float2 be  = ((const float2*)s_be)[e2];
            wc0 = fmaf(ww.x, wea.x, fmaf(ww.y, web.x, wc0));
            wc1 = fmaf(ww.x, wea.y, fmaf(ww.y, web.y, wc1));
            bc  = fmaf(ww.x, be.x,  fmaf(ww.y, be.y,  bc));
        }
        s_wc[n] = make_float4(4.0f * wc0, 4.0f * wc1, bc + b_ih[n] + b_hh[n], 0.f);
    }
    for (int i = tid; i < steps * AG; i += NTHR) {
        int t = i >> 2, a = i & 3;
        int agent = s_agent[a];
        const float* f0 = (t < T_obs)
            ? obs  + ((size_t)t * N + agent) * 2
            : pred + ((size_t)(t - T_obs) * N + agent) * 2;
        int t1 = t + 1;
        const float* f1 = (t1 < T_obs)
            ? obs  + ((size_t)t1 * N + agent) * 2
            : pred + ((size_t)(t1 - T_obs) * N + agent) * 2;
        float x0 = f0[0], y0 = f0[1], x1 = f1[0], y1 = f1[1];
        bool m = !(isnan(x0) || isnan(x1));
        s_vel[i] = make_float2(m ? (x1 - x0) : 0.f, m ? (y1 - y0) : 0.f);
        s_msk[i] = m ? 1.f : 0.f;
    }
    __syncthreads();   // Wif reads complete before W_hh overwrite

    // ===== phase C: stage W_hh f16, W1, W2; zero Xs (both buffers) =========
    for (int i = tid; i < GATES * HID / 4; i += NTHR) {
        float4 v = ((const float4*)W_hh)[i];
        int row = i >> 5;
        int c4  = (i & 31) << 2;
        __half* p = Ws + row * KP + c4;
        *(__half2*)(p)     = __floats2half2_rn(v.x, v.y);
        *(__half2*)(p + 2) = __floats2half2_rn(v.z, v.w);
    }
    #pragma unroll
    for (int k = 0; k < 4; k++) {
        int i = tid + 512 * k;
        float4 v = ((const float4*)W1)[i];
        int row = i >> 5;
        int col = (i & 31) << 2;
        float* p = W1s + row * PW1 + col;
        p[0] = v.x; p[1] = v.y; p[2] = v.z; p[3] = v.w;
    }
    {
        int i = tid;
        float4 v = ((const float4*)W2)[i];
        int row = i >> 4;
        int col = (i & 15) << 2;
        float* p = W2s + row * PW2 + col;
        p[0] = v.x; p[1] = v.y; p[2] = v.z; p[3] = v.w;
    }
    ((uint32_t*)Xs)[tid] = 0u;        // zero buffer 0+1 (4096 B total)
    ((uint32_t*)Xs)[tid + 512] = 0u;
    __syncthreads();

    // ===== phase D: hoist A fragments (W_hh) + fold coefs ==================
    uint32_t A0[8][4], A1[8][4];
    {
        const __half* g0 = Ws + (0 * 128 + u) * KP;
        const __half* g1 = Ws + (1 * 128 + u) * KP;
        const __half* g2 = Ws + (2 * 128 + u) * KP;
        const __half* g3 = Ws + (3 * 128 + u) * KP;
        #pragma unroll
        for (int kc = 0; kc < 8; kc++) {
            const int k = kc * 16 + 2 * q;
            A0[kc][0] = *(const uint32_t*)(g0 + k);
            A0[kc][1] = *(const uint32_t*)(g1 + k);
            A0[kc][2] = *(const uint32_t*)(g0 + k + 8);
            A0[kc][3] = *(const uint32_t*)(g1 + k + 8);
            A1[kc][0] = *(const uint32_t*)(g2 + k);
            A1[kc][1] = *(const uint32_t*)(g3 + k);
            A1[kc][2] = *(const uint32_t*)(g2 + k + 8);
            A1[kc][3] = *(const uint32_t*)(g3 + k + 8);
        }
    }
    float wc0[4], wc1[4], bcr[4];
    #pragma unroll
    for (int g = 0; g < 4; g++) {
        float4 wc = s_wc[g * 128 + u];
        wc0[g] = wc.x; wc1[g] = wc.y; bcr[g] = wc.z;
    }

    float c0 = 0.f, h0 = 0.f;           // single cell: (agent q, unit u)

    // SMEM raw addresses (Xs: [buf][unit 0..127][col 0..7] halves)
    const uint32_t xs_base = (uint32_t)__cvta_generic_to_shared(Xs);
    const uint32_t ldm_off = xs_base + lane * 16;            // ldmatrix rows
    const uint32_t sts_off = xs_base + u * 16 + q * 4;       // col 2q (b16)

    // =========================== recurrence ===============================
    for (int t = 0; t < steps; t++) {
        const int cur = t & 1, nxt = cur ^ 1;

        // vel + mask for this thread's agent
        float2 v2 = s_vel[t * AG + q];
        const bool m = (s_msk[t * AG + q] != 0.f);

        // accumulators: seeds go in the a-chain (cols 2q only are used)
        float d0a[4], d0b[4], d1a[4], d1b[4];
        d0a[0] = fmaf(v2.x, wc0[0], fmaf(v2.y, wc1[0], bcr[0]));
        d0a[2] = fmaf(v2.x, wc0[1], fmaf(v2.y, wc1[1], bcr[1]));
        d1a[0] = fmaf(v2.x, wc0[2], fmaf(v2.y, wc1[2], bcr[2]));
        d1a[2] = fmaf(v2.x, wc0[3], fmaf(v2.y, wc1[3], bcr[3]));
        d0a[1] = 0.f; d0a[3] = 0.f; d1a[1] = 0.f; d1a[3] = 0.f;
        #pragma unroll
        for (int i = 0; i < 4; i++) { d0b[i] = 0.f; d1b[i] = 0.f; }

        __syncthreads();   // h(t) stores visible

        // B frags via ldmatrix.trans; chunk c covers kc=2c and 2c+1
        const uint32_t xc = ldm_off + cur * 2048;
        #pragma unroll
        for (int cch = 0; cch < 4; cch++) {
            uint32_t b0a, b1a, b0b, b1b;
            asm volatile(
                "ldmatrix.sync.aligned.m8n8.x4.trans.shared.b16 "
                "{%0,%1,%2,%3}, [%4];"
                : "=r"(b0a), "=r"(b1a), "=r"(b0b), "=r"(b1b)
                : "r"(xc + cch * 512));
            mma16816(d0a, A0[2 * cch],     b0a, b1a);
            mma16816(d1a, A1[2 * cch],     b0a, b1a);
            mma16816(d0b, A0[2 * cch + 1], b0b, b1b);
            mma16816(d1b, A1[2 * cch + 1], b0b, b1b);
        }

        // only the col-2q elements matter: d[0] (gate row r), d[2] (row r+8)
        float gi_ = d0a[0] + d0b[0];   // gate0 = i
        float gf_ = d0a[2] + d0b[2];   // gate1 = f
        float gg_ = d1a[0] + d1b[0];   // gate2 = g
        float go_ = d1a[2] + d1b[2];   // gate3 = o

        float iv = sigf (gi_);
        float fv = sigf (gf_);
        float gv = tanha(gg_);
        float ov = sigf (go_);
        float c2 = fmaf(fv, c0, iv * gv);
        float h2 = ov * tanha(c2);
        if (m) { c0 = c2; h0 = h2; }

        // h store: Xs[nxt][u][col 2q] (odd cols remain zero)
        {
            __half hh = __float2half_rn(h0);
            asm volatile("st.shared.b16 [%0], %1;"
                         :: "r"(sts_off + nxt * 2048),
                            "h"(*(const uint16_t*)&hh));
        }
    }

    // =========================== fused MLP tail ===========================
    sh[q * HID + u] = h0;
    __syncthreads();

    // layer 1: (4 x 128) @ W1^T -> relu
    if (tid < 256) {
        const int u1 = tid & 63;
        const int a  = tid >> 6;
        float acc = b1[u1];
        const float* wr = W1s + u1 * PW1;
        const float* hv = sh + a * HID;
        #pragma unroll
        for (int k = 0; k < HID; k++) acc = fmaf(wr[k], hv[k], acc);
        s1[a * 64 + u1] = fmaxf(acc, 0.f);
    }
    __syncthreads();

    // layer 2: (4 x 64) @ W2^T -> relu
    if (tid < 128) {
        const int u2 = tid & 31;
        const int a  = tid >> 5;
        float acc = b2[u2];
        const float* wr = W2s + u2 * PW2;
        const float* xv = s1 + a * 64;
        #pragma unroll
        for (int k = 0; k < 64; k++) acc = fmaf(wr[k], xv[k], acc);
        s2[a * 32 + u2] = fmaxf(acc, 0.f);
    }
    __syncthreads();

    // layer 3
    if (tid < AG) {
        float acc = b3[0];
        #pragma unroll
        for (int k = 0; k < 32; k++) acc += W3[k] * s2[tid * 32 + k];
        out[row0 + tid] = fmaxf(acc, 0.f);
    }
}

// ------------------------------- launcher ----------------------------------
extern "C" void kernel_launch(void* const* d_in, const int* in_sizes, int n_in,
                              void* d_out, int out_size) {
    const float* observed   = (const float*)d_in[0];
    const float* prediction = (const float*)d_in[1];
    const void*  bsplit     = d_in[3];
    const float* W_emb      = (const float*)d_in[4];
    const float* b_emb      = (const float*)d_in[5];
    const float* W_ih       = (const float*)d_in[6];
    const float* W_hh       = (const float*)d_in[7];
    const float* b_ih       = (const float*)d_in[8];
    const float* b_hh       = (const float*)d_in[9];
    const float* W1         = (const float*)d_in[10];
    const float* b1         = (const float*)d_in[11];
    const float* W2         = (const float*)d_in[12];
    const float* b2         = (const float*)d_in[13];
    const float* W3         = (const float*)d_in[14];
    const float* b3         = (const float*)d_in[15];
    float* out = (float*)d_out;

    const int N      = in_sizes[2] / 2;               // goals: (N,2)
    const int T_obs  = in_sizes[0] / (2 * N);
    const int T_pred = in_sizes[1] / (2 * N);
    int steps = T_obs + T_pred - 1;
    if (steps > MAXSTEPS) steps = MAXSTEPS;

    cudaFuncSetAttribute(fused_kernel, cudaFuncAttributeMaxDynamicSharedMemorySize,
                         SMEM_TOTAL);

    fused_kernel<<<NBLK, NTHR, SMEM_TOTAL>>>(
        observed, prediction, bsplit,
        W_emb, b_emb, W_ih, W_hh, b_ih, b_hh,
        W1, b1, W2, b2, W3, b3,
        out, N, T_obs, steps);
}